// round 1
// baseline (speedup 1.0000x reference)
#include <cuda_runtime.h>
#include <math.h>

#define HDIM 256
#define F_IN 128
#define NMAX 100000
#define EPS 1e-5f

// Scratch (allocation-free rule: __device__ globals)
__device__ float g_bufH[(size_t)NMAX * HDIM];   // GEMM output (message source)
__device__ float g_bufO[(size_t)NMAX * HDIM];   // layer-1 accumulator / LN output
__device__ double g_scal[4];                    // [sum, sumsq] x 2 layers

__global__ void k_zero_scal() {
    if (threadIdx.x < 4) g_scal[threadIdx.x] = 0.0;
}

// out[n, c] = bias[c], vectorized float4. n4 = N * 64
__global__ void k_init(float* __restrict__ out, const float* __restrict__ bias, int n4) {
    int i = blockIdx.x * blockDim.x + threadIdx.x;
    if (i < n4) {
        ((float4*)out)[i] = ((const float4*)bias)[i & 63];
    }
}

// C[M, 256] = A[M, K] @ B[K, 256]. BM=BN=64, BK=16, 256 thr, 4x4 microtile.
__global__ __launch_bounds__(256) void k_gemm(const float* __restrict__ A,
                                              const float* __restrict__ B,
                                              float* __restrict__ C,
                                              int M, int K) {
    __shared__ float As[16][64];
    __shared__ float Bs[16][64];
    int tid = threadIdx.x;
    int tx = tid & 15, ty = tid >> 4;
    int m0 = blockIdx.y * 64;
    int n0 = blockIdx.x * 64;

    float acc[4][4] = {};

    int arow = tid >> 2;        // 0..63
    int acol = (tid & 3) * 4;   // 0,4,8,12
    int brow = tid >> 4;        // 0..15
    int bcol = (tid & 15) * 4;  // 0..60

    for (int k0 = 0; k0 < K; k0 += 16) {
        float4 av;
        if (m0 + arow < M)
            av = *(const float4*)(A + (size_t)(m0 + arow) * K + k0 + acol);
        else
            av = make_float4(0.f, 0.f, 0.f, 0.f);
        As[acol + 0][arow] = av.x;
        As[acol + 1][arow] = av.y;
        As[acol + 2][arow] = av.z;
        As[acol + 3][arow] = av.w;
        *(float4*)&Bs[brow][bcol] =
            *(const float4*)(B + (size_t)(k0 + brow) * HDIM + n0 + bcol);
        __syncthreads();
#pragma unroll
        for (int k = 0; k < 16; k++) {
            float4 ra = *(float4*)&As[k][ty * 4];
            float4 rb = *(float4*)&Bs[k][tx * 4];
            acc[0][0] += ra.x * rb.x; acc[0][1] += ra.x * rb.y;
            acc[0][2] += ra.x * rb.z; acc[0][3] += ra.x * rb.w;
            acc[1][0] += ra.y * rb.x; acc[1][1] += ra.y * rb.y;
            acc[1][2] += ra.y * rb.z; acc[1][3] += ra.y * rb.w;
            acc[2][0] += ra.z * rb.x; acc[2][1] += ra.z * rb.y;
            acc[2][2] += ra.z * rb.z; acc[2][3] += ra.z * rb.w;
            acc[3][0] += ra.w * rb.x; acc[3][1] += ra.w * rb.y;
            acc[3][2] += ra.w * rb.z; acc[3][3] += ra.w * rb.w;
        }
        __syncthreads();
    }
#pragma unroll
    for (int i = 0; i < 4; i++) {
        int row = m0 + ty * 4 + i;
        if (row < M) {
            float4 v = make_float4(acc[i][0], acc[i][1], acc[i][2], acc[i][3]);
            *(float4*)(C + (size_t)row * HDIM + n0 + tx * 4) = v;
        }
    }
}

// One warp per edge. out[dst] += ew * h[src], 256 channels via 2x float4/lane.
__global__ __launch_bounds__(256) void k_scatter(const float* __restrict__ h,
                                                 const int* __restrict__ ei,
                                                 const float* __restrict__ ew,
                                                 float* __restrict__ out, int E) {
    int warp = (blockIdx.x * blockDim.x + threadIdx.x) >> 5;
    int lane = threadIdx.x & 31;
    if (warp >= E) return;
    int src = __ldg(&ei[warp]);
    int dst = __ldg(&ei[E + warp]);
    float w = __ldg(&ew[warp]);
    const float4* hs = (const float4*)(h + (size_t)src * HDIM);
    float4* od = (float4*)(out + (size_t)dst * HDIM);
#pragma unroll
    for (int it = 0; it < 2; it++) {
        int c = lane + it * 32;
        float4 v = __ldg(&hs[c]);
        v.x *= w; v.y *= w; v.z *= w; v.w *= w;
        asm volatile("red.global.add.v4.f32 [%0], {%1,%2,%3,%4};"
                     :: "l"(od + c), "f"(v.x), "f"(v.y), "f"(v.z), "f"(v.w)
                     : "memory");
    }
}

// Global sum/sumsq over n4 float4s into g_scal[which], g_scal[which+1].
__global__ __launch_bounds__(256) void k_reduce(const float* __restrict__ x,
                                                int n4, int which) {
    __shared__ double sh[512];
    size_t i = (size_t)blockIdx.x * blockDim.x + threadIdx.x;
    size_t stride = (size_t)gridDim.x * blockDim.x;
    float s = 0.f, q = 0.f;
    for (; i < (size_t)n4; i += stride) {
        float4 v = ((const float4*)x)[i];
        s += v.x + v.y + v.z + v.w;
        q += v.x * v.x + v.y * v.y + v.z * v.z + v.w * v.w;
    }
    sh[threadIdx.x] = (double)s;
    sh[256 + threadIdx.x] = (double)q;
    __syncthreads();
    for (int o = 128; o > 0; o >>= 1) {
        if (threadIdx.x < (unsigned)o) {
            sh[threadIdx.x] += sh[threadIdx.x + o];
            sh[256 + threadIdx.x] += sh[256 + threadIdx.x + o];
        }
        __syncthreads();
    }
    if (threadIdx.x == 0) {
        atomicAdd(&g_scal[which], sh[0]);
        atomicAdd(&g_scal[which + 1], sh[256]);
    }
}

// In-place graph LayerNorm: y = (x - mean)/(std + EPS) * w[c] + b[c]
__global__ __launch_bounds__(256) void k_ln(float* __restrict__ x,
                                            const float* __restrict__ w,
                                            const float* __restrict__ b,
                                            int n4, int which) {
    int i = blockIdx.x * blockDim.x + threadIdx.x;
    if (i >= n4) return;
    double n = (double)n4 * 4.0;
    double m = g_scal[which] / n;
    double var = g_scal[which + 1] / n - m * m;
    float mean = (float)m;
    float inv = 1.f / ((float)sqrt(var) + EPS);
    float4 v = ((float4*)x)[i];
    int c4 = i & 63;
    float4 wv = ((const float4*)w)[c4];
    float4 bv = ((const float4*)b)[c4];
    v.x = (v.x - mean) * inv * wv.x + bv.x;
    v.y = (v.y - mean) * inv * wv.y + bv.y;
    v.z = (v.z - mean) * inv * wv.z + bv.z;
    v.w = (v.w - mean) * inv * wv.w + bv.w;
    ((float4*)x)[i] = v;
}

extern "C" void kernel_launch(void* const* d_in, const int* in_sizes, int n_in,
                              void* d_out, int out_size) {
    const float* x = (const float*)d_in[0];
    const int* ei[4] = {(const int*)d_in[1], (const int*)d_in[3],
                        (const int*)d_in[5], (const int*)d_in[7]};
    const float* ew[4] = {(const float*)d_in[2], (const float*)d_in[4],
                          (const float*)d_in[6], (const float*)d_in[8]};
    const float* W1 = (const float*)d_in[9];
    const float* b1 = (const float*)d_in[10];
    const float* W2 = (const float*)d_in[11];
    const float* b2 = (const float*)d_in[12];
    const float* ln1w = (const float*)d_in[13];
    const float* ln1b = (const float*)d_in[14];
    const float* ln2w = (const float*)d_in[15];
    const float* ln2b = (const float*)d_in[16];

    int N = in_sizes[0] / F_IN;
    int E = in_sizes[1] / 2;
    int n4 = N * (HDIM / 4);

    float *bufH, *bufO;
    cudaGetSymbolAddress((void**)&bufH, g_bufH);
    cudaGetSymbolAddress((void**)&bufO, g_bufO);
    float* out = (float*)d_out;

    dim3 gg(HDIM / 64, (N + 63) / 64);
    int initBlocks = (n4 + 255) / 256;
    int scatBlocks = (E + 7) / 8;

    k_zero_scal<<<1, 32>>>();

    // ---- Layer 1 ----
    k_gemm<<<gg, 256>>>(x, W1, bufH, N, F_IN);
    k_init<<<initBlocks, 256>>>(bufO, b1, n4);
    for (int r = 0; r < 4; r++)
        k_scatter<<<scatBlocks, 256>>>(bufH, ei[r], ew[r], bufO, E);
    k_reduce<<<1776, 256>>>(bufO, n4, 0);
    k_ln<<<initBlocks, 256>>>(bufO, ln1w, ln1b, n4, 0);

    // ---- Layer 2 ----
    k_gemm<<<gg, 256>>>(bufO, W2, bufH, N, HDIM);
    k_init<<<initBlocks, 256>>>(out, b2, n4);
    for (int r = 0; r < 4; r++)
        k_scatter<<<scatBlocks, 256>>>(bufH, ei[r], ew[r], out, E);
    k_reduce<<<1776, 256>>>(out, n4, 2);
    k_ln<<<initBlocks, 256>>>(out, ln2w, ln2b, n4, 2);
}

// round 2
// speedup vs baseline: 1.3453x; 1.3453x over previous
#include <cuda_runtime.h>
#include <math.h>

#define HDIM 256
#define F_IN 128
#define NMAX 100000
#define EMAX 1600000
#define ETOT (4 * EMAX)
#define EPS 1e-5f

// Scratch (allocation-free rule: __device__ globals)
__device__ float g_bufH[(size_t)NMAX * HDIM];   // GEMM output (message source)
__device__ float g_bufO[(size_t)NMAX * HDIM];   // layer-1 aggregate
__device__ int2  g_edges[ETOT];                 // CSR payload: (src, w-bits)
__device__ int   g_rowptr[NMAX + 1];
__device__ int   g_pos[NMAX];
__device__ int   g_deg[NMAX];
__device__ double g_scal[4];                    // [sum, sumsq] x 2 layers

__global__ void k_zero_scal() {
    if (threadIdx.x < 4) g_scal[threadIdx.x] = 0.0;
}

__global__ void k_zero_deg(int* __restrict__ deg, int N) {
    int i = blockIdx.x * blockDim.x + threadIdx.x;
    if (i < N) deg[i] = 0;
}

// Histogram of destination nodes for one relation.
__global__ __launch_bounds__(256) void k_hist(const int* __restrict__ ei,
                                              int* __restrict__ deg, int E) {
    int e = blockIdx.x * blockDim.x + threadIdx.x;
    if (e < E) atomicAdd(&deg[ei[E + e]], 1);
}

// Single-block exclusive scan over deg -> rowptr (and pos copy).
__global__ __launch_bounds__(1024) void k_scan(const int* __restrict__ deg,
                                               int* __restrict__ rowptr,
                                               int* __restrict__ pos, int N) {
    __shared__ int sh[1024];
    __shared__ int carry;
    if (threadIdx.x == 0) carry = 0;
    __syncthreads();
    for (int base = 0; base < N; base += 1024) {
        int i = base + threadIdx.x;
        int v = (i < N) ? deg[i] : 0;
        sh[threadIdx.x] = v;
        __syncthreads();
        for (int o = 1; o < 1024; o <<= 1) {
            int t = (threadIdx.x >= (unsigned)o) ? sh[threadIdx.x - o] : 0;
            __syncthreads();
            sh[threadIdx.x] += t;
            __syncthreads();
        }
        int c = carry;
        int excl = sh[threadIdx.x] - v + c;
        if (i < N) { rowptr[i] = excl; pos[i] = excl; }
        if (i == N - 1) rowptr[N] = excl + v;
        __syncthreads();
        if (threadIdx.x == 1023) carry = c + sh[1023];
        __syncthreads();
    }
}

// Fill CSR payload for one relation.
__global__ __launch_bounds__(256) void k_fill(const int* __restrict__ ei,
                                              const float* __restrict__ ew,
                                              int* __restrict__ pos,
                                              int2* __restrict__ edges, int E) {
    int e = blockIdx.x * blockDim.x + threadIdx.x;
    if (e < E) {
        int dst = ei[E + e];
        int p = atomicAdd(&pos[dst], 1);
        edges[p] = make_int2(ei[e], __float_as_int(ew[e]));
    }
}

// One block per dst node, one thread per channel. acc = bias + sum w*h[src].
__global__ __launch_bounds__(256) void k_gather(const float* __restrict__ h,
                                                const int2* __restrict__ edges,
                                                const int* __restrict__ rowptr,
                                                const float* __restrict__ bias,
                                                float* __restrict__ out) {
    int n = blockIdx.x;
    int c = threadIdx.x;
    int e = __ldg(&rowptr[n]);
    int e1 = __ldg(&rowptr[n + 1]);
    float acc = __ldg(&bias[c]);
    for (; e + 4 <= e1; e += 4) {
        int2 ea = __ldg(&edges[e]);
        int2 eb = __ldg(&edges[e + 1]);
        int2 ec = __ldg(&edges[e + 2]);
        int2 ed = __ldg(&edges[e + 3]);
        float va = __ldg(&h[(size_t)ea.x * HDIM + c]);
        float vb = __ldg(&h[(size_t)eb.x * HDIM + c]);
        float vc = __ldg(&h[(size_t)ec.x * HDIM + c]);
        float vd = __ldg(&h[(size_t)ed.x * HDIM + c]);
        acc += __int_as_float(ea.y) * va;
        acc += __int_as_float(eb.y) * vb;
        acc += __int_as_float(ec.y) * vc;
        acc += __int_as_float(ed.y) * vd;
    }
    for (; e < e1; e++) {
        int2 ea = __ldg(&edges[e]);
        acc += __int_as_float(ea.y) * __ldg(&h[(size_t)ea.x * HDIM + c]);
    }
    out[(size_t)n * HDIM + c] = acc;
}

// C[M, 256] = A[M, K] @ B[K, 256]. BM=BN=64, BK=16, 256 thr, 4x4 microtile.
__global__ __launch_bounds__(256) void k_gemm(const float* __restrict__ A,
                                              const float* __restrict__ B,
                                              float* __restrict__ C,
                                              int M, int K) {
    __shared__ float As[16][64];
    __shared__ float Bs[16][64];
    int tid = threadIdx.x;
    int tx = tid & 15, ty = tid >> 4;
    int m0 = blockIdx.y * 64;
    int n0 = blockIdx.x * 64;

    float acc[4][4] = {};

    int arow = tid >> 2;
    int acol = (tid & 3) * 4;
    int brow = tid >> 4;
    int bcol = (tid & 15) * 4;

    for (int k0 = 0; k0 < K; k0 += 16) {
        float4 av;
        if (m0 + arow < M)
            av = *(const float4*)(A + (size_t)(m0 + arow) * K + k0 + acol);
        else
            av = make_float4(0.f, 0.f, 0.f, 0.f);
        As[acol + 0][arow] = av.x;
        As[acol + 1][arow] = av.y;
        As[acol + 2][arow] = av.z;
        As[acol + 3][arow] = av.w;
        *(float4*)&Bs[brow][bcol] =
            *(const float4*)(B + (size_t)(k0 + brow) * HDIM + n0 + bcol);
        __syncthreads();
#pragma unroll
        for (int k = 0; k < 16; k++) {
            float4 ra = *(float4*)&As[k][ty * 4];
            float4 rb = *(float4*)&Bs[k][tx * 4];
            acc[0][0] += ra.x * rb.x; acc[0][1] += ra.x * rb.y;
            acc[0][2] += ra.x * rb.z; acc[0][3] += ra.x * rb.w;
            acc[1][0] += ra.y * rb.x; acc[1][1] += ra.y * rb.y;
            acc[1][2] += ra.y * rb.z; acc[1][3] += ra.y * rb.w;
            acc[2][0] += ra.z * rb.x; acc[2][1] += ra.z * rb.y;
            acc[2][2] += ra.z * rb.z; acc[2][3] += ra.z * rb.w;
            acc[3][0] += ra.w * rb.x; acc[3][1] += ra.w * rb.y;
            acc[3][2] += ra.w * rb.z; acc[3][3] += ra.w * rb.w;
        }
        __syncthreads();
    }
#pragma unroll
    for (int i = 0; i < 4; i++) {
        int row = m0 + ty * 4 + i;
        if (row < M) {
            float4 v = make_float4(acc[i][0], acc[i][1], acc[i][2], acc[i][3]);
            *(float4*)(C + (size_t)row * HDIM + n0 + tx * 4) = v;
        }
    }
}

// Global sum/sumsq over n4 float4s into g_scal[which], g_scal[which+1].
__global__ __launch_bounds__(256) void k_reduce(const float* __restrict__ x,
                                                int n4, int which) {
    __shared__ double sh[512];
    size_t i = (size_t)blockIdx.x * blockDim.x + threadIdx.x;
    size_t stride = (size_t)gridDim.x * blockDim.x;
    float s = 0.f, q = 0.f;
    for (; i < (size_t)n4; i += stride) {
        float4 v = ((const float4*)x)[i];
        s += v.x + v.y + v.z + v.w;
        q += v.x * v.x + v.y * v.y + v.z * v.z + v.w * v.w;
    }
    sh[threadIdx.x] = (double)s;
    sh[256 + threadIdx.x] = (double)q;
    __syncthreads();
    for (int o = 128; o > 0; o >>= 1) {
        if (threadIdx.x < (unsigned)o) {
            sh[threadIdx.x] += sh[threadIdx.x + o];
            sh[256 + threadIdx.x] += sh[256 + threadIdx.x + o];
        }
        __syncthreads();
    }
    if (threadIdx.x == 0) {
        atomicAdd(&g_scal[which], sh[0]);
        atomicAdd(&g_scal[which + 1], sh[256]);
    }
}

// In-place graph LayerNorm: y = (x - mean)/(std + EPS) * w[c] + b[c]
__global__ __launch_bounds__(256) void k_ln(float* __restrict__ x,
                                            const float* __restrict__ w,
                                            const float* __restrict__ b,
                                            int n4, int which) {
    int i = blockIdx.x * blockDim.x + threadIdx.x;
    if (i >= n4) return;
    double n = (double)n4 * 4.0;
    double m = g_scal[which] / n;
    double var = g_scal[which + 1] / n - m * m;
    float mean = (float)m;
    float inv = 1.f / ((float)sqrt(var) + EPS);
    float4 v = ((float4*)x)[i];
    int c4 = i & 63;
    float4 wv = ((const float4*)w)[c4];
    float4 bv = ((const float4*)b)[c4];
    v.x = (v.x - mean) * inv * wv.x + bv.x;
    v.y = (v.y - mean) * inv * wv.y + bv.y;
    v.z = (v.z - mean) * inv * wv.z + bv.z;
    v.w = (v.w - mean) * inv * wv.w + bv.w;
    ((float4*)x)[i] = v;
}

extern "C" void kernel_launch(void* const* d_in, const int* in_sizes, int n_in,
                              void* d_out, int out_size) {
    const float* x = (const float*)d_in[0];
    const int* ei[4] = {(const int*)d_in[1], (const int*)d_in[3],
                        (const int*)d_in[5], (const int*)d_in[7]};
    const float* ew[4] = {(const float*)d_in[2], (const float*)d_in[4],
                          (const float*)d_in[6], (const float*)d_in[8]};
    const float* W1 = (const float*)d_in[9];
    const float* b1 = (const float*)d_in[10];
    const float* W2 = (const float*)d_in[11];
    const float* b2 = (const float*)d_in[12];
    const float* ln1w = (const float*)d_in[13];
    const float* ln1b = (const float*)d_in[14];
    const float* ln2w = (const float*)d_in[15];
    const float* ln2b = (const float*)d_in[16];

    int N = in_sizes[0] / F_IN;
    int E = in_sizes[1] / 2;
    int n4 = N * (HDIM / 4);

    float *bufH, *bufO;
    int2* edges;
    int *rowptr, *pos, *deg;
    cudaGetSymbolAddress((void**)&bufH, g_bufH);
    cudaGetSymbolAddress((void**)&bufO, g_bufO);
    cudaGetSymbolAddress((void**)&edges, g_edges);
    cudaGetSymbolAddress((void**)&rowptr, g_rowptr);
    cudaGetSymbolAddress((void**)&pos, g_pos);
    cudaGetSymbolAddress((void**)&deg, g_deg);
    float* out = (float*)d_out;

    dim3 gg(HDIM / 64, (N + 63) / 64);
    int initBlocks = (n4 + 255) / 256;
    int eBlocks = (E + 255) / 256;

    k_zero_scal<<<1, 32>>>();

    // ---- Build combined CSR over the 4 relations (shared by both layers) ----
    k_zero_deg<<<(N + 255) / 256, 256>>>(deg, N);
    for (int r = 0; r < 4; r++) k_hist<<<eBlocks, 256>>>(ei[r], deg, E);
    k_scan<<<1, 1024>>>(deg, rowptr, pos, N);
    for (int r = 0; r < 4; r++) k_fill<<<eBlocks, 256>>>(ei[r], ew[r], pos, edges, E);

    // ---- Layer 1 ----
    k_gemm<<<gg, 256>>>(x, W1, bufH, N, F_IN);
    k_gather<<<N, 256>>>(bufH, edges, rowptr, b1, bufO);
    k_reduce<<<1776, 256>>>(bufO, n4, 0);
    k_ln<<<initBlocks, 256>>>(bufO, ln1w, ln1b, n4, 0);

    // ---- Layer 2 ----
    k_gemm<<<gg, 256>>>(bufO, W2, bufH, N, HDIM);
    k_gather<<<N, 256>>>(bufH, edges, rowptr, b2, out);
    k_reduce<<<1776, 256>>>(out, n4, 2);
    k_ln<<<initBlocks, 256>>>(out, ln2w, ln2b, n4, 2);
}

// round 4
// speedup vs baseline: 2.5682x; 1.9090x over previous
#include <cuda_runtime.h>
#include <cuda_fp16.h>
#include <math.h>

#define HDIM 256
#define F_IN 128
#define NMAX 100000
#define EMAX 1600000
#define ETOT (4 * EMAX)
#define EPS 1e-5f

// Scratch (allocation-free rule: __device__ globals)
__device__ __half g_xh[(size_t)NMAX * F_IN];     // x in fp16 (gather-1 source)
__device__ float  g_agg[(size_t)NMAX * F_IN];    // layer-1 aggregate (pre-GEMM)
__device__ float  g_bufO[(size_t)NMAX * HDIM];   // GEMM1 output (pre-LN1)
__device__ __half g_h2h[(size_t)NMAX * HDIM];    // GEMM2 output fp16 (gather-2 source)
__device__ int2   g_edges[ETOT];                 // CSR payload: (src, w-bits)
__device__ int    g_rowptr[NMAX + 1];
__device__ int    g_pos[NMAX];
__device__ int    g_deg[NMAX];
__device__ int    g_bsum[128];
__device__ double g_scal[4];                     // [sum, sumsq] x 2 layers

__global__ void k_zero_scal() {
    if (threadIdx.x < 4) g_scal[threadIdx.x] = 0.0;
}

__global__ void k_zero_deg(int* __restrict__ deg, int N) {
    int i = blockIdx.x * blockDim.x + threadIdx.x;
    if (i < N) deg[i] = 0;
}

__global__ __launch_bounds__(256) void k_hist(const int* __restrict__ ei,
                                              int* __restrict__ deg, int E) {
    int e = blockIdx.x * blockDim.x + threadIdx.x;
    if (e < E) atomicAdd(&deg[ei[E + e]], 1);
}

// ---- 3-phase parallel exclusive scan (N <= 128*1024) ----
__global__ __launch_bounds__(1024) void k_scan1(const int* __restrict__ deg,
                                                int* __restrict__ rowptr, int N) {
    __shared__ int sh[1024];
    int tid = threadIdx.x;
    int i = blockIdx.x * 1024 + tid;
    int v = (i < N) ? deg[i] : 0;
    sh[tid] = v;
    __syncthreads();
    for (int o = 1; o < 1024; o <<= 1) {
        int t = (tid >= o) ? sh[tid - o] : 0;
        __syncthreads();
        sh[tid] += t;
        __syncthreads();
    }
    if (i < N) rowptr[i] = sh[tid] - v;   // local exclusive
    if (tid == 1023) g_bsum[blockIdx.x] = sh[1023];
}

__global__ __launch_bounds__(128) void k_scan2(int B) {
    __shared__ int sh[128];
    int tid = threadIdx.x;
    int v = (tid < B) ? g_bsum[tid] : 0;
    sh[tid] = v;
    __syncthreads();
    for (int o = 1; o < 128; o <<= 1) {
        int t = (tid >= o) ? sh[tid - o] : 0;
        __syncthreads();
        sh[tid] += t;
        __syncthreads();
    }
    if (tid < B) g_bsum[tid] = sh[tid] - v;  // exclusive block offsets
}

__global__ __launch_bounds__(1024) void k_scan3(int* __restrict__ rowptr,
                                                int* __restrict__ pos,
                                                const int* __restrict__ deg, int N) {
    int i = blockIdx.x * 1024 + threadIdx.x;
    if (i < N) {
        int r = rowptr[i] + g_bsum[i >> 10];
        rowptr[i] = r;
        pos[i] = r;
        if (i == N - 1) rowptr[N] = r + deg[i];
    }
}

__global__ __launch_bounds__(256) void k_fill(const int* __restrict__ ei,
                                              const float* __restrict__ ew,
                                              int* __restrict__ pos,
                                              int2* __restrict__ edges, int E) {
    int e = blockIdx.x * blockDim.x + threadIdx.x;
    if (e < E) {
        int dst = ei[E + e];
        int p = atomicAdd(&pos[dst], 1);
        edges[p] = make_int2(ei[e], __float_as_int(ew[e]));
    }
}

// float -> half conversion, n2 = count/2
__global__ __launch_bounds__(256) void k_convert(const float* __restrict__ in,
                                                 __half* __restrict__ out, int n2) {
    int i = blockIdx.x * blockDim.x + threadIdx.x;
    if (i < n2) {
        float2 v = ((const float2*)in)[i];
        ((__half2*)out)[i] = __floats2half2_rn(v.x, v.y);
    }
}

// Layer-1 gather: agg[n, 0:128] = sum_e w * xh[src]. Block=64, half2 per thread.
__global__ __launch_bounds__(64) void k_gather1(const __half2* __restrict__ X,
                                                const int2* __restrict__ edges,
                                                const int* __restrict__ rowptr,
                                                float* __restrict__ agg) {
    int n = blockIdx.x;
    int t = threadIdx.x;
    int e = __ldg(&rowptr[n]);
    int e1 = __ldg(&rowptr[n + 1]);
    float2 acc = make_float2(0.f, 0.f);
    for (; e + 4 <= e1; e += 4) {
        int2 ea = __ldg(&edges[e]);
        int2 eb = __ldg(&edges[e + 1]);
        int2 ec = __ldg(&edges[e + 2]);
        int2 ed = __ldg(&edges[e + 3]);
        float2 fa = __half22float2(__ldg(&X[(size_t)ea.x * 64 + t]));
        float2 fb = __half22float2(__ldg(&X[(size_t)eb.x * 64 + t]));
        float2 fc = __half22float2(__ldg(&X[(size_t)ec.x * 64 + t]));
        float2 fd = __half22float2(__ldg(&X[(size_t)ed.x * 64 + t]));
        float wa = __int_as_float(ea.y), wb = __int_as_float(eb.y);
        float wc = __int_as_float(ec.y), wd = __int_as_float(ed.y);
        acc.x += wa * fa.x + wb * fb.x + wc * fc.x + wd * fd.x;
        acc.y += wa * fa.y + wb * fb.y + wc * fc.y + wd * fd.y;
    }
    for (; e < e1; e++) {
        int2 ea = __ldg(&edges[e]);
        float2 fa = __half22float2(__ldg(&X[(size_t)ea.x * 64 + t]));
        float w = __int_as_float(ea.y);
        acc.x += w * fa.x;
        acc.y += w * fa.y;
    }
    ((float2*)agg)[(size_t)n * 64 + t] = acc;
}

// Layer-2 gather: out[n, 0:256] = b2 + sum_e w * h2h[src]; + LN stats into g_scal[2,3].
__global__ __launch_bounds__(128) void k_gather2(const __half2* __restrict__ H,
                                                 const int2* __restrict__ edges,
                                                 const int* __restrict__ rowptr,
                                                 const float* __restrict__ bias,
                                                 float* __restrict__ out) {
    __shared__ double sh[256];
    int n = blockIdx.x;
    int t = threadIdx.x;
    int e = __ldg(&rowptr[n]);
    int e1 = __ldg(&rowptr[n + 1]);
    float2 bv = __ldg(&((const float2*)bias)[t]);
    float2 acc = bv;
    for (; e + 4 <= e1; e += 4) {
        int2 ea = __ldg(&edges[e]);
        int2 eb = __ldg(&edges[e + 1]);
        int2 ec = __ldg(&edges[e + 2]);
        int2 ed = __ldg(&edges[e + 3]);
        float2 fa = __half22float2(__ldg(&H[(size_t)ea.x * 128 + t]));
        float2 fb = __half22float2(__ldg(&H[(size_t)eb.x * 128 + t]));
        float2 fc = __half22float2(__ldg(&H[(size_t)ec.x * 128 + t]));
        float2 fd = __half22float2(__ldg(&H[(size_t)ed.x * 128 + t]));
        float wa = __int_as_float(ea.y), wb = __int_as_float(eb.y);
        float wc = __int_as_float(ec.y), wd = __int_as_float(ed.y);
        acc.x += wa * fa.x + wb * fb.x + wc * fc.x + wd * fd.x;
        acc.y += wa * fa.y + wb * fb.y + wc * fc.y + wd * fd.y;
    }
    for (; e < e1; e++) {
        int2 ea = __ldg(&edges[e]);
        float2 fa = __half22float2(__ldg(&H[(size_t)ea.x * 128 + t]));
        float w = __int_as_float(ea.y);
        acc.x += w * fa.x;
        acc.y += w * fa.y;
    }
    ((float2*)out)[(size_t)n * 128 + t] = acc;
    // LN stats
    sh[t] = (double)acc.x + (double)acc.y;
    sh[128 + t] = (double)(acc.x * acc.x) + (double)(acc.y * acc.y);
    __syncthreads();
    for (int o = 64; o > 0; o >>= 1) {
        if (t < o) {
            sh[t] += sh[t + o];
            sh[128 + t] += sh[128 + t + o];
        }
        __syncthreads();
    }
    if (t == 0) {
        atomicAdd(&g_scal[2], sh[0]);
        atomicAdd(&g_scal[3], sh[128]);
    }
}

// GEMM1: C[M,256] = A[M,128] @ B + bias; LN stats into g_scal[0,1].
__global__ __launch_bounds__(256) void k_gemm1(const float* __restrict__ A,
                                               const float* __restrict__ B,
                                               const float* __restrict__ bias,
                                               float* __restrict__ C, int M) {
    const int K = F_IN;
    __shared__ float As[16][64];
    __shared__ float Bs[16][64];
    __shared__ double sds[512];
    int tid = threadIdx.x;
    int tx = tid & 15, ty = tid >> 4;
    int m0 = blockIdx.y * 64;
    int n0 = blockIdx.x * 64;

    float acc[4][4] = {};
    int arow = tid >> 2;
    int acol = (tid & 3) * 4;
    int brow = tid >> 4;
    int bcol = (tid & 15) * 4;

    for (int k0 = 0; k0 < K; k0 += 16) {
        float4 av;
        if (m0 + arow < M)
            av = *(const float4*)(A + (size_t)(m0 + arow) * K + k0 + acol);
        else
            av = make_float4(0.f, 0.f, 0.f, 0.f);
        As[acol + 0][arow] = av.x;
        As[acol + 1][arow] = av.y;
        As[acol + 2][arow] = av.z;
        As[acol + 3][arow] = av.w;
        *(float4*)&Bs[brow][bcol] =
            *(const float4*)(B + (size_t)(k0 + brow) * HDIM + n0 + bcol);
        __syncthreads();
#pragma unroll
        for (int k = 0; k < 16; k++) {
            float4 ra = *(float4*)&As[k][ty * 4];
            float4 rb = *(float4*)&Bs[k][tx * 4];
            acc[0][0] += ra.x * rb.x; acc[0][1] += ra.x * rb.y;
            acc[0][2] += ra.x * rb.z; acc[0][3] += ra.x * rb.w;
            acc[1][0] += ra.y * rb.x; acc[1][1] += ra.y * rb.y;
            acc[1][2] += ra.y * rb.z; acc[1][3] += ra.y * rb.w;
            acc[2][0] += ra.z * rb.x; acc[2][1] += ra.z * rb.y;
            acc[2][2] += ra.z * rb.z; acc[2][3] += ra.z * rb.w;
            acc[3][0] += ra.w * rb.x; acc[3][1] += ra.w * rb.y;
            acc[3][2] += ra.w * rb.z; acc[3][3] += ra.w * rb.w;
        }
        __syncthreads();
    }
    float4 bvv = *(const float4*)(bias + n0 + tx * 4);
    float s = 0.f, q = 0.f;
#pragma unroll
    for (int i = 0; i < 4; i++) {
        int row = m0 + ty * 4 + i;
        if (row < M) {
            float4 v = make_float4(acc[i][0] + bvv.x, acc[i][1] + bvv.y,
                                   acc[i][2] + bvv.z, acc[i][3] + bvv.w);
            *(float4*)(C + (size_t)row * HDIM + n0 + tx * 4) = v;
            s += v.x + v.y + v.z + v.w;
            q += v.x * v.x + v.y * v.y + v.z * v.z + v.w * v.w;
        }
    }
    sds[tid] = (double)s;
    sds[256 + tid] = (double)q;
    __syncthreads();
    for (int o = 128; o > 0; o >>= 1) {
        if (tid < o) {
            sds[tid] += sds[tid + o];
            sds[256 + tid] += sds[256 + tid + o];
        }
        __syncthreads();
    }
    if (tid == 0) {
        atomicAdd(&g_scal[0], sds[0]);
        atomicAdd(&g_scal[1], sds[256]);
    }
}

// GEMM2: C_h16[M,256] = LN1(A)[M,256] @ B. LN1 affine applied on A-load.
__global__ __launch_bounds__(256) void k_gemm2(const float* __restrict__ A,
                                               const float* __restrict__ B,
                                               const float* __restrict__ lnw,
                                               const float* __restrict__ lnb,
                                               __half* __restrict__ C, int M) {
    const int K = HDIM;
    __shared__ float As[16][64];
    __shared__ float Bs[16][64];
    int tid = threadIdx.x;
    int tx = tid & 15, ty = tid >> 4;
    int m0 = blockIdx.y * 64;
    int n0 = blockIdx.x * 64;

    double nn = (double)M * HDIM;
    double m = g_scal[0] / nn;
    double var = g_scal[1] / nn - m * m;
    float mean = (float)m;
    float inv = 1.f / ((float)sqrt(var) + EPS);

    float acc[4][4] = {};
    int arow = tid >> 2;
    int acol = (tid & 3) * 4;
    int brow = tid >> 4;
    int bcol = (tid & 15) * 4;

    for (int k0 = 0; k0 < K; k0 += 16) {
        float4 av;
        if (m0 + arow < M)
            av = *(const float4*)(A + (size_t)(m0 + arow) * K + k0 + acol);
        else
            av = make_float4(0.f, 0.f, 0.f, 0.f);
        float4 lw = *(const float4*)(lnw + k0 + acol);
        float4 lb = *(const float4*)(lnb + k0 + acol);
        av.x = (av.x - mean) * inv * lw.x + lb.x;
        av.y = (av.y - mean) * inv * lw.y + lb.y;
        av.z = (av.z - mean) * inv * lw.z + lb.z;
        av.w = (av.w - mean) * inv * lw.w + lb.w;
        As[acol + 0][arow] = av.x;
        As[acol + 1][arow] = av.y;
        As[acol + 2][arow] = av.z;
        As[acol + 3][arow] = av.w;
        *(float4*)&Bs[brow][bcol] =
            *(const float4*)(B + (size_t)(k0 + brow) * HDIM + n0 + bcol);
        __syncthreads();
#pragma unroll
        for (int k = 0; k < 16; k++) {
            float4 ra = *(float4*)&As[k][ty * 4];
            float4 rb = *(float4*)&Bs[k][tx * 4];
            acc[0][0] += ra.x * rb.x; acc[0][1] += ra.x * rb.y;
            acc[0][2] += ra.x * rb.z; acc[0][3] += ra.x * rb.w;
            acc[1][0] += ra.y * rb.x; acc[1][1] += ra.y * rb.y;
            acc[1][2] += ra.y * rb.z; acc[1][3] += ra.y * rb.w;
            acc[2][0] += ra.z * rb.x; acc[2][1] += ra.z * rb.y;
            acc[2][2] += ra.z * rb.z; acc[2][3] += ra.z * rb.w;
            acc[3][0] += ra.w * rb.x; acc[3][1] += ra.w * rb.y;
            acc[3][2] += ra.w * rb.z; acc[3][3] += ra.w * rb.w;
        }
        __syncthreads();
    }
#pragma unroll
    for (int i = 0; i < 4; i++) {
        int row = m0 + ty * 4 + i;
        if (row < M) {
            __half2 h0 = __floats2half2_rn(acc[i][0], acc[i][1]);
            __half2 h1 = __floats2half2_rn(acc[i][2], acc[i][3]);
            __half2* dst = (__half2*)(C + (size_t)row * HDIM + n0 + tx * 4);
            dst[0] = h0;
            dst[1] = h1;
        }
    }
}

// Final in-place graph LayerNorm on out (stats in g_scal[2,3]).
__global__ __launch_bounds__(256) void k_ln(float* __restrict__ x,
                                            const float* __restrict__ w,
                                            const float* __restrict__ b,
                                            int n4, int which) {
    int i = blockIdx.x * blockDim.x + threadIdx.x;
    if (i >= n4) return;
    double n = (double)n4 * 4.0;
    double m = g_scal[which] / n;
    double var = g_scal[which + 1] / n - m * m;
    float mean = (float)m;
    float inv = 1.f / ((float)sqrt(var) + EPS);
    float4 v = ((float4*)x)[i];
    int c4 = i & 63;
    float4 wv = ((const float4*)w)[c4];
    float4 bv = ((const float4*)b)[c4];
    v.x = (v.x - mean) * inv * wv.x + bv.x;
    v.y = (v.y - mean) * inv * wv.y + bv.y;
    v.z = (v.z - mean) * inv * wv.z + bv.z;
    v.w = (v.w - mean) * inv * wv.w + bv.w;
    ((float4*)x)[i] = v;
}

extern "C" void kernel_launch(void* const* d_in, const int* in_sizes, int n_in,
                              void* d_out, int out_size) {
    const float* x = (const float*)d_in[0];
    const int* ei[4] = {(const int*)d_in[1], (const int*)d_in[3],
                        (const int*)d_in[5], (const int*)d_in[7]};
    const float* ew[4] = {(const float*)d_in[2], (const float*)d_in[4],
                          (const float*)d_in[6], (const float*)d_in[8]};
    const float* W1 = (const float*)d_in[9];
    const float* b1 = (const float*)d_in[10];
    const float* W2 = (const float*)d_in[11];
    const float* b2 = (const float*)d_in[12];
    const float* ln1w = (const float*)d_in[13];
    const float* ln1b = (const float*)d_in[14];
    const float* ln2w = (const float*)d_in[15];
    const float* ln2b = (const float*)d_in[16];

    int N = in_sizes[0] / F_IN;
    int E = in_sizes[1] / 2;
    int n4 = N * (HDIM / 4);

    __half *xh, *h2h;
    float *agg, *bufO;
    int2* edges;
    int *rowptr, *pos, *deg;
    cudaGetSymbolAddress((void**)&xh, g_xh);
    cudaGetSymbolAddress((void**)&h2h, g_h2h);
    cudaGetSymbolAddress((void**)&agg, g_agg);
    cudaGetSymbolAddress((void**)&bufO, g_bufO);
    cudaGetSymbolAddress((void**)&edges, g_edges);
    cudaGetSymbolAddress((void**)&rowptr, g_rowptr);
    cudaGetSymbolAddress((void**)&pos, g_pos);
    cudaGetSymbolAddress((void**)&deg, g_deg);
    float* out = (float*)d_out;

    dim3 gg(HDIM / 64, (N + 63) / 64);
    int initBlocks = (n4 + 255) / 256;
    int eBlocks = (E + 255) / 256;
    int scanB = (N + 1023) / 1024;

    k_zero_scal<<<1, 32>>>();

    // ---- CSR build (4 relations combined; shared by both layers) ----
    k_zero_deg<<<(N + 255) / 256, 256>>>(deg, N);
    for (int r = 0; r < 4; r++) k_hist<<<eBlocks, 256>>>(ei[r], deg, E);
    k_scan1<<<scanB, 1024>>>(deg, rowptr, N);
    k_scan2<<<1, 128>>>(scanB);
    k_scan3<<<scanB, 1024>>>(rowptr, pos, deg, N);
    for (int r = 0; r < 4; r++) k_fill<<<eBlocks, 256>>>(ei[r], ew[r], pos, edges, E);

    // ---- Layer 1: aggregate x (128-d, fp16), then GEMM (+bias, +LN stats) ----
    k_convert<<<(N * F_IN / 2 + 255) / 256, 256>>>(x, xh, N * F_IN / 2);
    k_gather1<<<N, 64>>>((const __half2*)xh, edges, rowptr, agg);
    k_gemm1<<<gg, 256>>>(agg, W1, b1, bufO, N);

    // ---- Layer 2: GEMM with fused LN1 affine on A, fp16 output; gather (+b2, +stats) ----
    k_gemm2<<<gg, 256>>>(bufO, W2, ln1w, ln1b, h2h, N);
    k_gather2<<<N, 128>>>((const __half2*)h2h, edges, rowptr, b2, out);
    k_ln<<<initBlocks, 256>>>(out, ln2w, ln2b, n4, 2);
}

// round 9
// speedup vs baseline: 2.9073x; 1.1320x over previous
#include <cuda_runtime.h>
#include <cuda_fp16.h>
#include <math.h>

#define HDIM 256
#define F_IN 128
#define NMAX 100000
#define EMAX 1600000
#define ETOT (4 * EMAX)
#define EPS 1e-5f

// Scratch (allocation-free rule: __device__ globals)
__device__ __half g_xh[(size_t)NMAX * F_IN];     // x in fp16 (gather-1 source)
__device__ float  g_agg[(size_t)NMAX * F_IN];    // layer-1 aggregate (pre-GEMM)
__device__ __half g_h1h[(size_t)NMAX * HDIM];    // GEMM1 output fp16 (pre-LN1, GEMM2 A)
__device__ __half g_h2h[(size_t)NMAX * HDIM];    // GEMM2 output fp16 (gather-2 source)
__device__ float  g_W2f[HDIM * HDIM];            // a_k * W2[k][n] (LN1 folded)
__device__ float  g_avec[HDIM];
__device__ float  g_dvec[HDIM];                  // c @ W2
__device__ int2   g_edges[ETOT];                 // CSR payload: (src, w-bits)
__device__ int    g_rowptr[NMAX + 1];
__device__ int    g_pos[NMAX];
__device__ int    g_deg[NMAX];
__device__ int    g_bsum[128];
__device__ double g_scal[4];                     // [sum, sumsq] x 2 layers

__global__ void k_zero_scal() {
    if (threadIdx.x < 4) g_scal[threadIdx.x] = 0.0;
}

__global__ void k_zero_deg(int* __restrict__ deg, int N) {
    int i = blockIdx.x * blockDim.x + threadIdx.x;
    if (i < N) deg[i] = 0;
}

__global__ __launch_bounds__(256) void k_hist(const int* __restrict__ ei,
                                              int* __restrict__ deg, int E) {
    int e = blockIdx.x * blockDim.x + threadIdx.x;
    if (e < E) atomicAdd(&deg[ei[E + e]], 1);
}

// ---- 3-phase parallel exclusive scan (N <= 128*1024) ----
__global__ __launch_bounds__(1024) void k_scan1(const int* __restrict__ deg,
                                                int* __restrict__ rowptr, int N) {
    __shared__ int sh[1024];
    int tid = threadIdx.x;
    int i = blockIdx.x * 1024 + tid;
    int v = (i < N) ? deg[i] : 0;
    sh[tid] = v;
    __syncthreads();
    for (int o = 1; o < 1024; o <<= 1) {
        int t = (tid >= o) ? sh[tid - o] : 0;
        __syncthreads();
        sh[tid] += t;
        __syncthreads();
    }
    if (i < N) rowptr[i] = sh[tid] - v;
    if (tid == 1023) g_bsum[blockIdx.x] = sh[1023];
}

__global__ __launch_bounds__(128) void k_scan2(int B) {
    __shared__ int sh[128];
    int tid = threadIdx.x;
    int v = (tid < B) ? g_bsum[tid] : 0;
    sh[tid] = v;
    __syncthreads();
    for (int o = 1; o < 128; o <<= 1) {
        int t = (tid >= o) ? sh[tid - o] : 0;
        __syncthreads();
        sh[tid] += t;
        __syncthreads();
    }
    if (tid < B) g_bsum[tid] = sh[tid] - v;
}

__global__ __launch_bounds__(1024) void k_scan3(int* __restrict__ rowptr,
                                                int* __restrict__ pos,
                                                const int* __restrict__ deg, int N) {
    int i = blockIdx.x * 1024 + threadIdx.x;
    if (i < N) {
        int r = rowptr[i] + g_bsum[i >> 10];
        rowptr[i] = r;
        pos[i] = r;
        if (i == N - 1) rowptr[N] = r + deg[i];
    }
}

__global__ __launch_bounds__(256) void k_fill(const int* __restrict__ ei,
                                              const float* __restrict__ ew,
                                              int* __restrict__ pos,
                                              int2* __restrict__ edges, int E) {
    int e = blockIdx.x * blockDim.x + threadIdx.x;
    if (e < E) {
        int dst = ei[E + e];
        int p = atomicAdd(&pos[dst], 1);
        edges[p] = make_int2(ei[e], __float_as_int(ew[e]));
    }
}

// float -> half conversion, n2 = count/2
__global__ __launch_bounds__(256) void k_convert(const float* __restrict__ in,
                                                 __half* __restrict__ out, int n2) {
    int i = blockIdx.x * blockDim.x + threadIdx.x;
    if (i < n2) {
        float2 v = ((const float2*)in)[i];
        ((__half2*)out)[i] = __floats2half2_rn(v.x, v.y);
    }
}

__device__ __forceinline__ float4 fma4_u2(float4 acc, unsigned lo, unsigned hi, float w) {
    __half2 h0 = *(__half2*)&lo;
    __half2 h1 = *(__half2*)&hi;
    float2 f0 = __half22float2(h0);
    float2 f1 = __half22float2(h1);
    acc.x += w * f0.x; acc.y += w * f0.y;
    acc.z += w * f1.x; acc.w += w * f1.y;
    return acc;
}

// Layer-1 gather: agg[n, 0:128] = sum_e w * xh[src]. One warp per node, uint2/lane.
__global__ __launch_bounds__(32) void k_gather1(const uint2* __restrict__ X,
                                                const int2* __restrict__ edges,
                                                const int* __restrict__ rowptr,
                                                float* __restrict__ agg) {
    int n = blockIdx.x;
    int t = threadIdx.x;           // 0..31, 4 channels each
    int e = __ldg(&rowptr[n]);
    int e1 = __ldg(&rowptr[n + 1]);
    float4 acc = make_float4(0.f, 0.f, 0.f, 0.f);
    for (; e + 4 <= e1; e += 4) {
        int2 ea = __ldg(&edges[e]);
        int2 eb = __ldg(&edges[e + 1]);
        int2 ec = __ldg(&edges[e + 2]);
        int2 ed = __ldg(&edges[e + 3]);
        uint2 ua = __ldg(&X[(size_t)ea.x * 32 + t]);
        uint2 ub = __ldg(&X[(size_t)eb.x * 32 + t]);
        uint2 uc = __ldg(&X[(size_t)ec.x * 32 + t]);
        uint2 ud = __ldg(&X[(size_t)ed.x * 32 + t]);
        acc = fma4_u2(acc, ua.x, ua.y, __int_as_float(ea.y));
        acc = fma4_u2(acc, ub.x, ub.y, __int_as_float(eb.y));
        acc = fma4_u2(acc, uc.x, uc.y, __int_as_float(ec.y));
        acc = fma4_u2(acc, ud.x, ud.y, __int_as_float(ed.y));
    }
    for (; e < e1; e++) {
        int2 ea = __ldg(&edges[e]);
        uint2 ua = __ldg(&X[(size_t)ea.x * 32 + t]);
        acc = fma4_u2(acc, ua.x, ua.y, __int_as_float(ea.y));
    }
    ((float4*)agg)[(size_t)n * 32 + t] = acc;
}

// Layer-2 gather: out[n, 0:256] = b2 + sum_e w * h2h[src]; + LN stats into g_scal[2,3].
// 64 threads per node, uint2 (4 channels) per lane.
__global__ __launch_bounds__(64) void k_gather2(const uint2* __restrict__ H,
                                                const int2* __restrict__ edges,
                                                const int* __restrict__ rowptr,
                                                const float* __restrict__ bias,
                                                float* __restrict__ out) {
    __shared__ double sh[128];
    int n = blockIdx.x;
    int t = threadIdx.x;           // 0..63
    int e = __ldg(&rowptr[n]);
    int e1 = __ldg(&rowptr[n + 1]);
    float4 acc = __ldg(&((const float4*)bias)[t]);
    for (; e + 4 <= e1; e += 4) {
        int2 ea = __ldg(&edges[e]);
        int2 eb = __ldg(&edges[e + 1]);
        int2 ec = __ldg(&edges[e + 2]);
        int2 ed = __ldg(&edges[e + 3]);
        uint2 ua = __ldg(&H[(size_t)ea.x * 64 + t]);
        uint2 ub = __ldg(&H[(size_t)eb.x * 64 + t]);
        uint2 uc = __ldg(&H[(size_t)ec.x * 64 + t]);
        uint2 ud = __ldg(&H[(size_t)ed.x * 64 + t]);
        acc = fma4_u2(acc, ua.x, ua.y, __int_as_float(ea.y));
        acc = fma4_u2(acc, ub.x, ub.y, __int_as_float(eb.y));
        acc = fma4_u2(acc, uc.x, uc.y, __int_as_float(ec.y));
        acc = fma4_u2(acc, ud.x, ud.y, __int_as_float(ed.y));
    }
    for (; e < e1; e++) {
        int2 ea = __ldg(&edges[e]);
        uint2 ua = __ldg(&H[(size_t)ea.x * 64 + t]);
        acc = fma4_u2(acc, ua.x, ua.y, __int_as_float(ea.y));
    }
    ((float4*)out)[(size_t)n * 64 + t] = acc;
    // LN stats
    sh[t] = (double)acc.x + (double)acc.y + (double)acc.z + (double)acc.w;
    sh[64 + t] = (double)(acc.x * acc.x) + (double)(acc.y * acc.y) +
                 (double)(acc.z * acc.z) + (double)(acc.w * acc.w);
    __syncthreads();
    for (int o = 32; o > 0; o >>= 1) {
        if (t < o) {
            sh[t] += sh[t + o];
            sh[64 + t] += sh[64 + t + o];
        }
        __syncthreads();
    }
    if (t == 0) {
        atomicAdd(&g_scal[2], sh[0]);
        atomicAdd(&g_scal[3], sh[64]);
    }
}

// GEMM1: h1h[M,256] = fp16(A[M,128] @ W1 + b1); LN stats -> g_scal[0,1].
__global__ __launch_bounds__(256) void k_gemm1(const float* __restrict__ A,
                                               const float* __restrict__ B,
                                               const float* __restrict__ bias,
                                               __half* __restrict__ C, int M) {
    const int K = F_IN;
    __shared__ float As[16][64];
    __shared__ float Bs[16][64];
    __shared__ double sds[512];
    int tid = threadIdx.x;
    int tx = tid & 15, ty = tid >> 4;
    int m0 = blockIdx.y * 64;
    int n0 = blockIdx.x * 64;

    float acc[4][4] = {};
    int arow = tid >> 2;
    int acol = (tid & 3) * 4;
    int brow = tid >> 4;
    int bcol = (tid & 15) * 4;

    for (int k0 = 0; k0 < K; k0 += 16) {
        float4 av;
        if (m0 + arow < M)
            av = *(const float4*)(A + (size_t)(m0 + arow) * K + k0 + acol);
        else
            av = make_float4(0.f, 0.f, 0.f, 0.f);
        As[acol + 0][arow] = av.x;
        As[acol + 1][arow] = av.y;
        As[acol + 2][arow] = av.z;
        As[acol + 3][arow] = av.w;
        *(float4*)&Bs[brow][bcol] =
            *(const float4*)(B + (size_t)(k0 + brow) * HDIM + n0 + bcol);
        __syncthreads();
#pragma unroll
        for (int k = 0; k < 16; k++) {
            float4 ra = *(float4*)&As[k][ty * 4];
            float4 rb = *(float4*)&Bs[k][tx * 4];
            acc[0][0] += ra.x * rb.x; acc[0][1] += ra.x * rb.y;
            acc[0][2] += ra.x * rb.z; acc[0][3] += ra.x * rb.w;
            acc[1][0] += ra.y * rb.x; acc[1][1] += ra.y * rb.y;
            acc[1][2] += ra.y * rb.z; acc[1][3] += ra.y * rb.w;
            acc[2][0] += ra.z * rb.x; acc[2][1] += ra.z * rb.y;
            acc[2][2] += ra.z * rb.z; acc[2][3] += ra.z * rb.w;
            acc[3][0] += ra.w * rb.x; acc[3][1] += ra.w * rb.y;
            acc[3][2] += ra.w * rb.z; acc[3][3] += ra.w * rb.w;
        }
        __syncthreads();
    }
    float4 bvv = *(const float4*)(bias + n0 + tx * 4);
    float s = 0.f, q = 0.f;
#pragma unroll
    for (int i = 0; i < 4; i++) {
        int row = m0 + ty * 4 + i;
        if (row < M) {
            float v0 = acc[i][0] + bvv.x, v1 = acc[i][1] + bvv.y;
            float v2 = acc[i][2] + bvv.z, v3 = acc[i][3] + bvv.w;
            __half2* dst = (__half2*)(C + (size_t)row * HDIM + n0 + tx * 4);
            dst[0] = __floats2half2_rn(v0, v1);
            dst[1] = __floats2half2_rn(v2, v3);
            s += v0 + v1 + v2 + v3;
            q += v0 * v0 + v1 * v1 + v2 * v2 + v3 * v3;
        }
    }
    sds[tid] = (double)s;
    sds[256 + tid] = (double)q;
    __syncthreads();
    for (int o = 128; o > 0; o >>= 1) {
        if (tid < o) {
            sds[tid] += sds[tid + o];
            sds[256 + tid] += sds[256 + tid + o];
        }
        __syncthreads();
    }
    if (tid == 0) {
        atomicAdd(&g_scal[0], sds[0]);
        atomicAdd(&g_scal[1], sds[256]);
    }
}

// Fold LN1 into W2: a_k = inv*ln1w_k; c_k = ln1b_k - mean*a_k; d = c @ W2.
__global__ __launch_bounds__(256) void k_prep(const float* __restrict__ lnw,
                                              const float* __restrict__ lnb,
                                              const float* __restrict__ W2, int M) {
    __shared__ float cs[HDIM];
    int t = threadIdx.x;
    double nn = (double)M * HDIM;
    double mm = g_scal[0] / nn;
    double var = g_scal[1] / nn - mm * mm;
    float mean = (float)mm;
    float inv = 1.f / ((float)sqrt(var) + EPS);
    float a = inv * lnw[t];
    float c = lnb[t] - mean * a;
    g_avec[t] = a;
    cs[t] = c;
    __syncthreads();
    float d = 0.f;
    for (int k = 0; k < HDIM; k++) d += cs[k] * W2[k * HDIM + t];
    g_dvec[t] = d;
}

// W2f[k][n] = a_k * W2[k][n]
__global__ __launch_bounds__(256) void k_scaleW(const float* __restrict__ W2,
                                                float* __restrict__ W2f) {
    int k = blockIdx.x, n = threadIdx.x;
    W2f[k * HDIM + n] = g_avec[k] * W2[k * HDIM + n];
}

// GEMM2: h2h[M,256] = fp16( h1h[M,256](fp16) @ W2f + d ).
__global__ __launch_bounds__(256) void k_gemm2(const __half* __restrict__ A,
                                               const float* __restrict__ B,
                                               __half* __restrict__ C, int M) {
    const int K = HDIM;
    __shared__ float As[16][64];
    __shared__ float Bs[16][64];
    int tid = threadIdx.x;
    int tx = tid & 15, ty = tid >> 4;
    int m0 = blockIdx.y * 64;
    int n0 = blockIdx.x * 64;

    float acc[4][4] = {};
    int arow = tid >> 2;
    int acol = (tid & 3) * 4;
    int brow = tid >> 4;
    int bcol = (tid & 15) * 4;

    for (int k0 = 0; k0 < K; k0 += 16) {
        float4 av;
        if (m0 + arow < M) {
            uint2 u = *(const uint2*)(A + (size_t)(m0 + arow) * HDIM + k0 + acol);
            float2 f0 = __half22float2(*(__half2*)&u.x);
            float2 f1 = __half22float2(*(__half2*)&u.y);
            av = make_float4(f0.x, f0.y, f1.x, f1.y);
        } else {
            av = make_float4(0.f, 0.f, 0.f, 0.f);
        }
        As[acol + 0][arow] = av.x;
        As[acol + 1][arow] = av.y;
        As[acol + 2][arow] = av.z;
        As[acol + 3][arow] = av.w;
        *(float4*)&Bs[brow][bcol] =
            *(const float4*)(B + (size_t)(k0 + brow) * HDIM + n0 + bcol);
        __syncthreads();
#pragma unroll
        for (int k = 0; k < 16; k++) {
            float4 ra = *(float4*)&As[k][ty * 4];
            float4 rb = *(float4*)&Bs[k][tx * 4];
            acc[0][0] += ra.x * rb.x; acc[0][1] += ra.x * rb.y;
            acc[0][2] += ra.x * rb.z; acc[0][3] += ra.x * rb.w;
            acc[1][0] += ra.y * rb.x; acc[1][1] += ra.y * rb.y;
            acc[1][2] += ra.y * rb.z; acc[1][3] += ra.y * rb.w;
            acc[2][0] += ra.z * rb.x; acc[2][1] += ra.z * rb.y;
            acc[2][2] += ra.z * rb.z; acc[2][3] += ra.z * rb.w;
            acc[3][0] += ra.w * rb.x; acc[3][1] += ra.w * rb.y;
            acc[3][2] += ra.w * rb.z; acc[3][3] += ra.w * rb.w;
        }
        __syncthreads();
    }
    float4 dv = *(const float4*)(g_dvec + n0 + tx * 4);
#pragma unroll
    for (int i = 0; i < 4; i++) {
        int row = m0 + ty * 4 + i;
        if (row < M) {
            __half2* dst = (__half2*)(C + (size_t)row * HDIM + n0 + tx * 4);
            dst[0] = __floats2half2_rn(acc[i][0] + dv.x, acc[i][1] + dv.y);
            dst[1] = __floats2half2_rn(acc[i][2] + dv.z, acc[i][3] + dv.w);
        }
    }
}

// Final in-place graph LayerNorm on out (stats in g_scal[2,3]).
__global__ __launch_bounds__(256) void k_ln(float* __restrict__ x,
                                            const float* __restrict__ w,
                                            const float* __restrict__ b,
                                            int n4, int which) {
    int i = blockIdx.x * blockDim.x + threadIdx.x;
    if (i >= n4) return;
    double n = (double)n4 * 4.0;
    double m = g_scal[which] / n;
    double var = g_scal[which + 1] / n - m * m;
    float mean = (float)m;
    float inv = 1.f / ((float)sqrt(var) + EPS);
    float4 v = ((float4*)x)[i];
    int c4 = i & 63;
    float4 wv = ((const float4*)w)[c4];
    float4 bv = ((const float4*)b)[c4];
    v.x = (v.x - mean) * inv * wv.x + bv.x;
    v.y = (v.y - mean) * inv * wv.y + bv.y;
    v.z = (v.z - mean) * inv * wv.z + bv.z;
    v.w = (v.w - mean) * inv * wv.w + bv.w;
    ((float4*)x)[i] = v;
}

extern "C" void kernel_launch(void* const* d_in, const int* in_sizes, int n_in,
                              void* d_out, int out_size) {
    const float* x = (const float*)d_in[0];
    const int* ei[4] = {(const int*)d_in[1], (const int*)d_in[3],
                        (const int*)d_in[5], (const int*)d_in[7]};
    const float* ew[4] = {(const float*)d_in[2], (const float*)d_in[4],
                          (const float*)d_in[6], (const float*)d_in[8]};
    const float* W1 = (const float*)d_in[9];
    const float* b1 = (const float*)d_in[10];
    const float* W2 = (const float*)d_in[11];
    const float* b2 = (const float*)d_in[12];
    const float* ln1w = (const float*)d_in[13];
    const float* ln1b = (const float*)d_in[14];
    const float* ln2w = (const float*)d_in[15];
    const float* ln2b = (const float*)d_in[16];

    int N = in_sizes[0] / F_IN;
    int E = in_sizes[1] / 2;
    int n4 = N * (HDIM / 4);

    __half *xh, *h1h, *h2h;
    float *agg, *W2f;
    int2* edges;
    int *rowptr, *pos, *deg;
    cudaGetSymbolAddress((void**)&xh, g_xh);
    cudaGetSymbolAddress((void**)&h1h, g_h1h);
    cudaGetSymbolAddress((void**)&h2h, g_h2h);
    cudaGetSymbolAddress((void**)&agg, g_agg);
    cudaGetSymbolAddress((void**)&W2f, g_W2f);
    cudaGetSymbolAddress((void**)&edges, g_edges);
    cudaGetSymbolAddress((void**)&rowptr, g_rowptr);
    cudaGetSymbolAddress((void**)&pos, g_pos);
    cudaGetSymbolAddress((void**)&deg, g_deg);
    float* out = (float*)d_out;

    int initBlocks = (n4 + 255) / 256;
    int eBlocks = (E + 255) / 256;
    int scanB = (N + 1023) / 1024;
    dim3 gg(HDIM / 64, (N + 63) / 64);

    k_zero_scal<<<1, 32>>>();

    // ---- CSR build (4 relations combined; shared by both layers) ----
    k_zero_deg<<<(N + 255) / 256, 256>>>(deg, N);
    for (int r = 0; r < 4; r++) k_hist<<<eBlocks, 256>>>(ei[r], deg, E);
    k_scan1<<<scanB, 1024>>>(deg, rowptr, N);
    k_scan2<<<1, 128>>>(scanB);
    k_scan3<<<scanB, 1024>>>(rowptr, pos, deg, N);
    for (int r = 0; r < 4; r++) k_fill<<<eBlocks, 256>>>(ei[r], ew[r], pos, edges, E);

    // ---- Layer 1: convert x, aggregate (128-d fp16), GEMM (+bias, +stats, fp16 out) ----
    k_convert<<<(N * F_IN / 2 + 255) / 256, 256>>>(x, xh, N * F_IN / 2);
    k_gather1<<<N, 32>>>((const uint2*)xh, edges, rowptr, agg);
    k_gemm1<<<gg, 256>>>(agg, W1, b1, h1h, N);

    // ---- Fold LN1 into W2, then Layer 2 ----
    k_prep<<<1, 256>>>(ln1w, ln1b, W2, N);
    k_scaleW<<<HDIM, 256>>>(W2, W2f);
    k_gemm2<<<gg, 256>>>(h1h, W2f, h2h, N);
    k_gather2<<<N, 64>>>((const uint2*)h2h, edges, rowptr, b2, out);
    k_ln<<<initBlocks, 256>>>(out, ln2w, ln2b, n4, 2);
}

// round 10
// speedup vs baseline: 3.1026x; 1.0672x over previous
#include <cuda_runtime.h>
#include <cuda_fp16.h>
#include <math.h>

#define HDIM 256
#define F_IN 128
#define NMAX 100000
#define EMAX 1600000
#define ETOT (4 * EMAX)
#define EPS 1e-5f

// Scratch (allocation-free rule: __device__ globals)
__device__ __half g_xh[(size_t)NMAX * F_IN];     // x in fp16 (gather-1 source)
__device__ float  g_agg[(size_t)NMAX * F_IN];    // layer-1 aggregate (pre-GEMM)
__device__ __half g_h1h[(size_t)NMAX * HDIM];    // GEMM1 output fp16 (pre-LN1, GEMM2 A)
__device__ __half g_h2h[(size_t)NMAX * HDIM];    // GEMM2 output fp16 (gather-2 source)
__device__ float  g_W2f[HDIM * HDIM];            // a_k * W2[k][n] (LN1 folded)
__device__ float  g_avec[HDIM];
__device__ float  g_dvec[HDIM];                  // c @ W2
__device__ int2   g_edges[ETOT];                 // CSR payload: (src, w-bits)
__device__ int    g_rowptr[NMAX + 1];
__device__ int    g_pos[NMAX];
__device__ int    g_deg[NMAX];
__device__ int    g_bsum[128];
__device__ double g_scal[4];                     // [sum, sumsq] x 2 layers

// ---- packed f32x2 helpers (B300: 2x fp32 FMA rate, PTX-only pattern) ----
__device__ __forceinline__ unsigned long long pk2(float x, float y) {
    unsigned long long r;
    asm("mov.b64 %0, {%1, %2};" : "=l"(r) : "f"(x), "f"(y));
    return r;
}
__device__ __forceinline__ void upk2(unsigned long long v, float& x, float& y) {
    asm("mov.b64 {%0, %1}, %2;" : "=f"(x), "=f"(y) : "l"(v));
}
__device__ __forceinline__ unsigned long long ffma2(unsigned long long a,
                                                    unsigned long long b,
                                                    unsigned long long c) {
    unsigned long long d;
    asm("fma.rn.f32x2 %0, %1, %2, %3;" : "=l"(d) : "l"(a), "l"(b), "l"(c));
    return d;
}

__global__ void k_zero_scal() {
    if (threadIdx.x < 4) g_scal[threadIdx.x] = 0.0;
}

__global__ void k_zero_deg(int* __restrict__ deg, int N) {
    int i = blockIdx.x * blockDim.x + threadIdx.x;
    if (i < N) deg[i] = 0;
}

__global__ __launch_bounds__(256) void k_hist(const int* __restrict__ ei,
                                              int* __restrict__ deg, int E) {
    int e = blockIdx.x * blockDim.x + threadIdx.x;
    if (e < E) atomicAdd(&deg[ei[E + e]], 1);
}

// ---- 3-phase parallel exclusive scan (N <= 128*1024) ----
__global__ __launch_bounds__(1024) void k_scan1(const int* __restrict__ deg,
                                                int* __restrict__ rowptr, int N) {
    __shared__ int sh[1024];
    int tid = threadIdx.x;
    int i = blockIdx.x * 1024 + tid;
    int v = (i < N) ? deg[i] : 0;
    sh[tid] = v;
    __syncthreads();
    for (int o = 1; o < 1024; o <<= 1) {
        int t = (tid >= o) ? sh[tid - o] : 0;
        __syncthreads();
        sh[tid] += t;
        __syncthreads();
    }
    if (i < N) rowptr[i] = sh[tid] - v;
    if (tid == 1023) g_bsum[blockIdx.x] = sh[1023];
}

__global__ __launch_bounds__(128) void k_scan2(int B) {
    __shared__ int sh[128];
    int tid = threadIdx.x;
    int v = (tid < B) ? g_bsum[tid] : 0;
    sh[tid] = v;
    __syncthreads();
    for (int o = 1; o < 128; o <<= 1) {
        int t = (tid >= o) ? sh[tid - o] : 0;
        __syncthreads();
        sh[tid] += t;
        __syncthreads();
    }
    if (tid < B) g_bsum[tid] = sh[tid] - v;
}

__global__ __launch_bounds__(1024) void k_scan3(int* __restrict__ rowptr,
                                                int* __restrict__ pos,
                                                const int* __restrict__ deg, int N) {
    int i = blockIdx.x * 1024 + threadIdx.x;
    if (i < N) {
        int r = rowptr[i] + g_bsum[i >> 10];
        rowptr[i] = r;
        pos[i] = r;
        if (i == N - 1) rowptr[N] = r + deg[i];
    }
}

__global__ __launch_bounds__(256) void k_fill(const int* __restrict__ ei,
                                              const float* __restrict__ ew,
                                              int* __restrict__ pos,
                                              int2* __restrict__ edges, int E) {
    int e = blockIdx.x * blockDim.x + threadIdx.x;
    if (e < E) {
        int dst = ei[E + e];
        int p = atomicAdd(&pos[dst], 1);
        edges[p] = make_int2(ei[e], __float_as_int(ew[e]));
    }
}

// float -> half conversion, n2 = count/2
__global__ __launch_bounds__(256) void k_convert(const float* __restrict__ in,
                                                 __half* __restrict__ out, int n2) {
    int i = blockIdx.x * blockDim.x + threadIdx.x;
    if (i < n2) {
        float2 v = ((const float2*)in)[i];
        ((__half2*)out)[i] = __floats2half2_rn(v.x, v.y);
    }
}

__device__ __forceinline__ float4 fma4_u2(float4 acc, unsigned lo, unsigned hi, float w) {
    __half2 h0 = *(__half2*)&lo;
    __half2 h1 = *(__half2*)&hi;
    float2 f0 = __half22float2(h0);
    float2 f1 = __half22float2(h1);
    acc.x += w * f0.x; acc.y += w * f0.y;
    acc.z += w * f1.x; acc.w += w * f1.y;
    return acc;
}

// Layer-1 gather: agg[n, 0:128] = sum_e w * xh[src]. One warp per node, uint2/lane.
__global__ __launch_bounds__(32) void k_gather1(const uint2* __restrict__ X,
                                                const int2* __restrict__ edges,
                                                const int* __restrict__ rowptr,
                                                float* __restrict__ agg) {
    int n = blockIdx.x;
    int t = threadIdx.x;           // 0..31, 4 channels each
    int e = __ldg(&rowptr[n]);
    int e1 = __ldg(&rowptr[n + 1]);
    float4 acc = make_float4(0.f, 0.f, 0.f, 0.f);
    for (; e + 4 <= e1; e += 4) {
        int2 ea = __ldg(&edges[e]);
        int2 eb = __ldg(&edges[e + 1]);
        int2 ec = __ldg(&edges[e + 2]);
        int2 ed = __ldg(&edges[e + 3]);
        uint2 ua = __ldg(&X[(size_t)ea.x * 32 + t]);
        uint2 ub = __ldg(&X[(size_t)eb.x * 32 + t]);
        uint2 uc = __ldg(&X[(size_t)ec.x * 32 + t]);
        uint2 ud = __ldg(&X[(size_t)ed.x * 32 + t]);
        acc = fma4_u2(acc, ua.x, ua.y, __int_as_float(ea.y));
        acc = fma4_u2(acc, ub.x, ub.y, __int_as_float(eb.y));
        acc = fma4_u2(acc, uc.x, uc.y, __int_as_float(ec.y));
        acc = fma4_u2(acc, ud.x, ud.y, __int_as_float(ed.y));
    }
    for (; e < e1; e++) {
        int2 ea = __ldg(&edges[e]);
        uint2 ua = __ldg(&X[(size_t)ea.x * 32 + t]);
        acc = fma4_u2(acc, ua.x, ua.y, __int_as_float(ea.y));
    }
    ((float4*)agg)[(size_t)n * 32 + t] = acc;
}

// Layer-2 gather: out[n, 0:256] = b2 + sum_e w * h2h[src]; + LN stats into g_scal[2,3].
// 64 threads per node, uint2 (4 channels) per lane.
__global__ __launch_bounds__(64) void k_gather2(const uint2* __restrict__ H,
                                                const int2* __restrict__ edges,
                                                const int* __restrict__ rowptr,
                                                const float* __restrict__ bias,
                                                float* __restrict__ out) {
    __shared__ double sh[128];
    int n = blockIdx.x;
    int t = threadIdx.x;           // 0..63
    int e = __ldg(&rowptr[n]);
    int e1 = __ldg(&rowptr[n + 1]);
    float4 acc = __ldg(&((const float4*)bias)[t]);
    for (; e + 4 <= e1; e += 4) {
        int2 ea = __ldg(&edges[e]);
        int2 eb = __ldg(&edges[e + 1]);
        int2 ec = __ldg(&edges[e + 2]);
        int2 ed = __ldg(&edges[e + 3]);
        uint2 ua = __ldg(&H[(size_t)ea.x * 64 + t]);
        uint2 ub = __ldg(&H[(size_t)eb.x * 64 + t]);
        uint2 uc = __ldg(&H[(size_t)ec.x * 64 + t]);
        uint2 ud = __ldg(&H[(size_t)ed.x * 64 + t]);
        acc = fma4_u2(acc, ua.x, ua.y, __int_as_float(ea.y));
        acc = fma4_u2(acc, ub.x, ub.y, __int_as_float(eb.y));
        acc = fma4_u2(acc, uc.x, uc.y, __int_as_float(ec.y));
        acc = fma4_u2(acc, ud.x, ud.y, __int_as_float(ed.y));
    }
    for (; e < e1; e++) {
        int2 ea = __ldg(&edges[e]);
        uint2 ua = __ldg(&H[(size_t)ea.x * 64 + t]);
        acc = fma4_u2(acc, ua.x, ua.y, __int_as_float(ea.y));
    }
    ((float4*)out)[(size_t)n * 64 + t] = acc;
    // LN stats
    sh[t] = (double)acc.x + (double)acc.y + (double)acc.z + (double)acc.w;
    sh[64 + t] = (double)(acc.x * acc.x) + (double)(acc.y * acc.y) +
                 (double)(acc.z * acc.z) + (double)(acc.w * acc.w);
    __syncthreads();
    for (int o = 32; o > 0; o >>= 1) {
        if (t < o) {
            sh[t] += sh[t + o];
            sh[64 + t] += sh[64 + t + o];
        }
        __syncthreads();
    }
    if (t == 0) {
        atomicAdd(&g_scal[2], sh[0]);
        atomicAdd(&g_scal[3], sh[64]);
    }
}

// ---- Big-tile GEMM with packed f32x2 FMA ----
// C_h16[M,256] = A[M,K] @ B + bias(row-vec). Tile 128x128, BK=16, 256 thr, 8x8 micro.
// HALF_A: A is fp16 (row stride HDIM). EPI1: accumulate LN stats -> g_scal[0,1].
template<int K, bool HALF_A, bool EPI1>
__global__ __launch_bounds__(256) void k_gemm_big(const float* __restrict__ Af,
                                                  const __half* __restrict__ Ah,
                                                  const float* __restrict__ B,
                                                  const float* __restrict__ bias,
                                                  __half* __restrict__ C, int M) {
    __shared__ float sA[16 * 136];   // [k][m], stride 136
    __shared__ float sB[16 * 132];   // [k][n], stride 132
    __shared__ double sds[512];
    int tid = threadIdx.x;
    int tx = tid & 15, ty = tid >> 4;
    int m0 = blockIdx.y * 128, n0 = blockIdx.x * 128;

    unsigned long long acc[8][4];
#pragma unroll
    for (int i = 0; i < 8; i++)
#pragma unroll
        for (int j = 0; j < 4; j++) acc[i][j] = 0ull;

    for (int k0 = 0; k0 < K; k0 += 16) {
        // Stage A tile 128x16 (transposed to [k][m])
#pragma unroll
        for (int l = 0; l < 2; l++) {
            int f = l * 256 + tid;
            int row = f >> 2;          // 0..127
            int c4 = (f & 3) * 4;      // 0,4,8,12
            float v0, v1, v2, v3;
            if (m0 + row < M) {
                if (HALF_A) {
                    uint2 u = *(const uint2*)(Ah + (size_t)(m0 + row) * HDIM + k0 + c4);
                    float2 f0 = __half22float2(*(__half2*)&u.x);
                    float2 f1 = __half22float2(*(__half2*)&u.y);
                    v0 = f0.x; v1 = f0.y; v2 = f1.x; v3 = f1.y;
                } else {
                    float4 av = *(const float4*)(Af + (size_t)(m0 + row) * K + k0 + c4);
                    v0 = av.x; v1 = av.y; v2 = av.z; v3 = av.w;
                }
            } else {
                v0 = v1 = v2 = v3 = 0.f;
            }
            sA[(c4 + 0) * 136 + row] = v0;
            sA[(c4 + 1) * 136 + row] = v1;
            sA[(c4 + 2) * 136 + row] = v2;
            sA[(c4 + 3) * 136 + row] = v3;
        }
        // Stage B tile 16x128
#pragma unroll
        for (int l = 0; l < 2; l++) {
            int f = l * 256 + tid;
            int row = f >> 5;          // 0..15
            int c4 = (f & 31) * 4;     // 0..124
            *(float4*)&sB[row * 132 + c4] =
                *(const float4*)(B + (size_t)(k0 + row) * HDIM + n0 + c4);
        }
        __syncthreads();
#pragma unroll
        for (int k = 0; k < 16; k++) {
            float4 ra0 = *(const float4*)&sA[k * 136 + ty * 8];
            float4 ra1 = *(const float4*)&sA[k * 136 + ty * 8 + 4];
            ulonglong2 b01 = *(const ulonglong2*)&sB[k * 132 + tx * 8];
            ulonglong2 b23 = *(const ulonglong2*)&sB[k * 132 + tx * 8 + 4];
            float am[8] = {ra0.x, ra0.y, ra0.z, ra0.w, ra1.x, ra1.y, ra1.z, ra1.w};
#pragma unroll
            for (int i = 0; i < 8; i++) {
                unsigned long long pa = pk2(am[i], am[i]);
                acc[i][0] = ffma2(pa, b01.x, acc[i][0]);
                acc[i][1] = ffma2(pa, b01.y, acc[i][1]);
                acc[i][2] = ffma2(pa, b23.x, acc[i][2]);
                acc[i][3] = ffma2(pa, b23.y, acc[i][3]);
            }
        }
        __syncthreads();
    }

    // Epilogue: + bias row-vector, fp16 store; EPI1 also LN stats.
    float bv[8];
#pragma unroll
    for (int j = 0; j < 4; j++) {
        float2 b2 = *(const float2*)(bias + n0 + tx * 8 + j * 2);
        bv[2 * j] = b2.x;
        bv[2 * j + 1] = b2.y;
    }
    float s = 0.f, q = 0.f;
#pragma unroll
    for (int i = 0; i < 8; i++) {
        int row = m0 + ty * 8 + i;
        if (row < M) {
            __half2* dst = (__half2*)(C + (size_t)row * HDIM + n0 + tx * 8);
#pragma unroll
            for (int j = 0; j < 4; j++) {
                float lo, hi;
                upk2(acc[i][j], lo, hi);
                lo += bv[2 * j];
                hi += bv[2 * j + 1];
                dst[j] = __floats2half2_rn(lo, hi);
                if (EPI1) {
                    s += lo + hi;
                    q += lo * lo + hi * hi;
                }
            }
        }
    }
    if (EPI1) {
        sds[tid] = (double)s;
        sds[256 + tid] = (double)q;
        __syncthreads();
        for (int o = 128; o > 0; o >>= 1) {
            if (tid < o) {
                sds[tid] += sds[tid + o];
                sds[256 + tid] += sds[256 + tid + o];
            }
            __syncthreads();
        }
        if (tid == 0) {
            atomicAdd(&g_scal[0], sds[0]);
            atomicAdd(&g_scal[1], sds[256]);
        }
    }
}

// Fold LN1 into W2: a_k = inv*ln1w_k; c_k = ln1b_k - mean*a_k; d = c @ W2.
__global__ __launch_bounds__(256) void k_prep(const float* __restrict__ lnw,
                                              const float* __restrict__ lnb,
                                              const float* __restrict__ W2, int M) {
    __shared__ float cs[HDIM];
    int t = threadIdx.x;
    double nn = (double)M * HDIM;
    double mm = g_scal[0] / nn;
    double var = g_scal[1] / nn - mm * mm;
    float mean = (float)mm;
    float inv = 1.f / ((float)sqrt(var) + EPS);
    float a = inv * lnw[t];
    float c = lnb[t] - mean * a;
    g_avec[t] = a;
    cs[t] = c;
    __syncthreads();
    float d = 0.f;
    for (int k = 0; k < HDIM; k++) d += cs[k] * W2[k * HDIM + t];
    g_dvec[t] = d;
}

// W2f[k][n] = a_k * W2[k][n]
__global__ __launch_bounds__(256) void k_scaleW(const float* __restrict__ W2,
                                                float* __restrict__ W2f) {
    int k = blockIdx.x, n = threadIdx.x;
    W2f[k * HDIM + n] = g_avec[k] * W2[k * HDIM + n];
}

// Final in-place graph LayerNorm on out (stats in g_scal[2,3]).
__global__ __launch_bounds__(256) void k_ln(float* __restrict__ x,
                                            const float* __restrict__ w,
                                            const float* __restrict__ b,
                                            int n4, int which) {
    int i = blockIdx.x * blockDim.x + threadIdx.x;
    if (i >= n4) return;
    double n = (double)n4 * 4.0;
    double m = g_scal[which] / n;
    double var = g_scal[which + 1] / n - m * m;
    float mean = (float)m;
    float inv = 1.f / ((float)sqrt(var) + EPS);
    float4 v = ((float4*)x)[i];
    int c4 = i & 63;
    float4 wv = ((const float4*)w)[c4];
    float4 bv = ((const float4*)b)[c4];
    v.x = (v.x - mean) * inv * wv.x + bv.x;
    v.y = (v.y - mean) * inv * wv.y + bv.y;
    v.z = (v.z - mean) * inv * wv.z + bv.z;
    v.w = (v.w - mean) * inv * wv.w + bv.w;
    ((float4*)x)[i] = v;
}

extern "C" void kernel_launch(void* const* d_in, const int* in_sizes, int n_in,
                              void* d_out, int out_size) {
    const float* x = (const float*)d_in[0];
    const int* ei[4] = {(const int*)d_in[1], (const int*)d_in[3],
                        (const int*)d_in[5], (const int*)d_in[7]};
    const float* ew[4] = {(const float*)d_in[2], (const float*)d_in[4],
                          (const float*)d_in[6], (const float*)d_in[8]};
    const float* W1 = (const float*)d_in[9];
    const float* b1 = (const float*)d_in[10];
    const float* W2 = (const float*)d_in[11];
    const float* b2 = (const float*)d_in[12];
    const float* ln1w = (const float*)d_in[13];
    const float* ln1b = (const float*)d_in[14];
    const float* ln2w = (const float*)d_in[15];
    const float* ln2b = (const float*)d_in[16];

    int N = in_sizes[0] / F_IN;
    int E = in_sizes[1] / 2;
    int n4 = N * (HDIM / 4);

    __half *xh, *h1h, *h2h;
    float *agg, *W2f, *dvec;
    int2* edges;
    int *rowptr, *pos, *deg;
    cudaGetSymbolAddress((void**)&xh, g_xh);
    cudaGetSymbolAddress((void**)&h1h, g_h1h);
    cudaGetSymbolAddress((void**)&h2h, g_h2h);
    cudaGetSymbolAddress((void**)&agg, g_agg);
    cudaGetSymbolAddress((void**)&W2f, g_W2f);
    cudaGetSymbolAddress((void**)&dvec, g_dvec);
    cudaGetSymbolAddress((void**)&edges, g_edges);
    cudaGetSymbolAddress((void**)&rowptr, g_rowptr);
    cudaGetSymbolAddress((void**)&pos, g_pos);
    cudaGetSymbolAddress((void**)&deg, g_deg);
    float* out = (float*)d_out;

    int initBlocks = (n4 + 255) / 256;
    int eBlocks = (E + 255) / 256;
    int scanB = (N + 1023) / 1024;
    dim3 gbig(HDIM / 128, (N + 127) / 128);

    k_zero_scal<<<1, 32>>>();

    // ---- CSR build (4 relations combined; shared by both layers) ----
    k_zero_deg<<<(N + 255) / 256, 256>>>(deg, N);
    for (int r = 0; r < 4; r++) k_hist<<<eBlocks, 256>>>(ei[r], deg, E);
    k_scan1<<<scanB, 1024>>>(deg, rowptr, N);
    k_scan2<<<1, 128>>>(scanB);
    k_scan3<<<scanB, 1024>>>(rowptr, pos, deg, N);
    for (int r = 0; r < 4; r++) k_fill<<<eBlocks, 256>>>(ei[r], ew[r], pos, edges, E);

    // ---- Layer 1: convert x, aggregate (128-d fp16), GEMM (+bias, +stats, fp16 out) ----
    k_convert<<<(N * F_IN / 2 + 255) / 256, 256>>>(x, xh, N * F_IN / 2);
    k_gather1<<<N, 32>>>((const uint2*)xh, edges, rowptr, agg);
    k_gemm_big<F_IN, false, true><<<gbig, 256>>>(agg, nullptr, W1, b1, h1h, N);

    // ---- Fold LN1 into W2, then Layer 2 ----
    k_prep<<<1, 256>>>(ln1w, ln1b, W2, N);
    k_scaleW<<<HDIM, 256>>>(W2, W2f);
    k_gemm_big<HDIM, true, false><<<gbig, 256>>>(nullptr, h1h, W2f, dvec, h2h, N);
    k_gather2<<<N, 64>>>((const uint2*)h2h, edges, rowptr, b2, out);
    k_ln<<<initBlocks, 256>>>(out, ln2w, ln2b, n4, 2);
}

// round 11
// speedup vs baseline: 3.2515x; 1.0480x over previous
#include <cuda_runtime.h>
#include <cuda_fp16.h>
#include <math.h>

#define HDIM 256
#define F_IN 128
#define NMAX 100000
#define EMAX 1600000
#define ETOT (4 * EMAX)
#define EPS 1e-5f

// Scratch (allocation-free rule: __device__ globals)
__device__ __half g_xh[(size_t)NMAX * F_IN];     // x in fp16 (gather-1 source)
__device__ float  g_agg[(size_t)NMAX * F_IN];    // layer-1 aggregate (pre-GEMM)
__device__ __half g_h1h[(size_t)NMAX * HDIM];    // GEMM1 output fp16 (GEMM2 A)
__device__ __half g_h2h[(size_t)NMAX * HDIM];    // GEMM2 output fp16 (gather-2 source)
__device__ float  g_W2f[HDIM * HDIM];            // a_k * W2[k][n] (LN1 folded)
__device__ float  g_avec[HDIM];
__device__ float  g_dvec[HDIM];                  // c @ W2
__device__ int4   g_edges4[ETOT / 2];            // CSR payload, 16B-aligned
__device__ int    g_rowptr[NMAX + 1];
__device__ int    g_pos[NMAX];
__device__ int    g_deg[NMAX];
__device__ int    g_bsum[128];
__device__ double g_scal[4];                     // [sum, sumsq] x 2 layers

// ---- packed f32x2 helpers (B300: 2x fp32 FMA rate, PTX-only pattern) ----
__device__ __forceinline__ unsigned long long pk2(float x, float y) {
    unsigned long long r;
    asm("mov.b64 %0, {%1, %2};" : "=l"(r) : "f"(x), "f"(y));
    return r;
}
__device__ __forceinline__ void upk2(unsigned long long v, float& x, float& y) {
    asm("mov.b64 {%0, %1}, %2;" : "=f"(x), "=f"(y) : "l"(v));
}
__device__ __forceinline__ unsigned long long ffma2(unsigned long long a,
                                                    unsigned long long b,
                                                    unsigned long long c) {
    unsigned long long d;
    asm("fma.rn.f32x2 %0, %1, %2, %3;" : "=l"(d) : "l"(a), "l"(b), "l"(c));
    return d;
}

// Fused: float->half convert of x AND zero deg.
__global__ __launch_bounds__(256) void k_convert_zdeg(const float* __restrict__ in,
                                                      __half* __restrict__ out, int n2,
                                                      int* __restrict__ deg, int N) {
    int i = blockIdx.x * blockDim.x + threadIdx.x;
    if (i < n2) {
        float2 v = ((const float2*)in)[i];
        ((__half2*)out)[i] = __floats2half2_rn(v.x, v.y);
    }
    if (i < N) deg[i] = 0;
}

// Histogram over all 4 relations in one kernel.
__global__ __launch_bounds__(256) void k_hist_all(const int* __restrict__ e0,
                                                  const int* __restrict__ e1,
                                                  const int* __restrict__ e2,
                                                  const int* __restrict__ e3,
                                                  int* __restrict__ deg, int E) {
    int t = blockIdx.x * blockDim.x + threadIdx.x;
    const int* p;
    if (t < E) p = e0;
    else if (t < 2 * E) { p = e1; t -= E; }
    else if (t < 3 * E) { p = e2; t -= 2 * E; }
    else if (t < 4 * E) { p = e3; t -= 3 * E; }
    else return;
    atomicAdd(&deg[p[E + t]], 1);
}

// Scan phase 1 (+ zero g_scal).
__global__ __launch_bounds__(1024) void k_scan1z(const int* __restrict__ deg,
                                                 int* __restrict__ rowptr, int N) {
    __shared__ int sh[1024];
    int tid = threadIdx.x;
    if (blockIdx.x == 0 && tid < 4) g_scal[tid] = 0.0;
    int i = blockIdx.x * 1024 + tid;
    int v = (i < N) ? deg[i] : 0;
    sh[tid] = v;
    __syncthreads();
    for (int o = 1; o < 1024; o <<= 1) {
        int t = (tid >= o) ? sh[tid - o] : 0;
        __syncthreads();
        sh[tid] += t;
        __syncthreads();
    }
    if (i < N) rowptr[i] = sh[tid] - v;
    if (tid == 1023) g_bsum[blockIdx.x] = sh[1023];
}

// Scan phase 2+3 fused: each block reduces bsum[0..bid) itself.
__global__ __launch_bounds__(1024) void k_scan3b(int* __restrict__ rowptr,
                                                 int* __restrict__ pos,
                                                 const int* __restrict__ deg, int N) {
    __shared__ int sh[128];
    __shared__ int off;
    int tid = threadIdx.x;
    int bid = blockIdx.x;
    if (tid < 128) {
        int partial = 0;
        for (int j = tid; j < bid; j += 128) partial += g_bsum[j];
        sh[tid] = partial;
    }
    __syncthreads();
    if (tid == 0) {
        int s = 0;
        for (int j = 0; j < 128; j++) s += sh[j];
        off = s;
    }
    __syncthreads();
    int i = bid * 1024 + tid;
    if (i < N) {
        int r = rowptr[i] + off;
        rowptr[i] = r;
        pos[i] = r;
        if (i == N - 1) rowptr[N] = r + deg[i];
    }
}

// Fill CSR payload for all 4 relations in one kernel.
__global__ __launch_bounds__(256) void k_fill_all(const int* __restrict__ e0,
                                                  const float* __restrict__ w0,
                                                  const int* __restrict__ e1,
                                                  const float* __restrict__ w1,
                                                  const int* __restrict__ e2,
                                                  const float* __restrict__ w2,
                                                  const int* __restrict__ e3,
                                                  const float* __restrict__ w3,
                                                  int* __restrict__ pos, int E) {
    int t = blockIdx.x * blockDim.x + threadIdx.x;
    const int* p;
    const float* w;
    if (t < E) { p = e0; w = w0; }
    else if (t < 2 * E) { p = e1; w = w1; t -= E; }
    else if (t < 3 * E) { p = e2; w = w2; t -= 2 * E; }
    else if (t < 4 * E) { p = e3; w = w3; t -= 3 * E; }
    else return;
    int dst = p[E + t];
    int q = atomicAdd(&pos[dst], 1);
    ((int2*)g_edges4)[q] = make_int2(p[t], __float_as_int(w[t]));
}

__device__ __forceinline__ float4 fma4_u2(float4 acc, unsigned lo, unsigned hi, float w) {
    float2 f0 = __half22float2(*(__half2*)&lo);
    float2 f1 = __half22float2(*(__half2*)&hi);
    acc.x += w * f0.x; acc.y += w * f0.y;
    acc.z += w * f1.x; acc.w += w * f1.y;
    return acc;
}

// Layer-1 gather: agg[n, 0:128] = sum_e w * xh[src]. 1 warp/node, 2 nodes/block.
__global__ __launch_bounds__(64) void k_gather1(const uint2* __restrict__ X,
                                                const int* __restrict__ rowptr,
                                                float* __restrict__ agg, int N) {
    int n = blockIdx.x * 2 + (threadIdx.x >> 5);
    if (n >= N) return;
    int t = threadIdx.x & 31;
    const int2* edges = (const int2*)g_edges4;
    int e = __ldg(&rowptr[n]);
    int e1 = __ldg(&rowptr[n + 1]);
    float4 acc = make_float4(0.f, 0.f, 0.f, 0.f);
    if (e < e1 && (e & 1)) {
        int2 ea = __ldg(&edges[e]);
        uint2 u = __ldg(&X[(size_t)ea.x * 32 + t]);
        acc = fma4_u2(acc, u.x, u.y, __int_as_float(ea.y));
        e++;
    }
    for (; e + 4 <= e1; e += 4) {
        int4 p = __ldg((const int4*)&edges[e]);
        int4 q = __ldg((const int4*)&edges[e + 2]);
        uint2 u0 = __ldg(&X[(size_t)p.x * 32 + t]);
        uint2 u1 = __ldg(&X[(size_t)p.z * 32 + t]);
        uint2 u2 = __ldg(&X[(size_t)q.x * 32 + t]);
        uint2 u3 = __ldg(&X[(size_t)q.z * 32 + t]);
        acc = fma4_u2(acc, u0.x, u0.y, __int_as_float(p.y));
        acc = fma4_u2(acc, u1.x, u1.y, __int_as_float(p.w));
        acc = fma4_u2(acc, u2.x, u2.y, __int_as_float(q.y));
        acc = fma4_u2(acc, u3.x, u3.y, __int_as_float(q.w));
    }
    for (; e < e1; e++) {
        int2 ea = __ldg(&edges[e]);
        uint2 u = __ldg(&X[(size_t)ea.x * 32 + t]);
        acc = fma4_u2(acc, u.x, u.y, __int_as_float(ea.y));
    }
    ((float4*)agg)[(size_t)n * 32 + t] = acc;
}

// Layer-2 gather: out[n, 0:256] = b2 + sum_e w * h2h[src]; + LN stats -> g_scal[2,3].
// 1 warp/node (uint4 = 8 channels/lane), 2 nodes/block, shfl stats.
__global__ __launch_bounds__(64) void k_gather2(const uint4* __restrict__ H,
                                                const int* __restrict__ rowptr,
                                                const float* __restrict__ bias,
                                                float* __restrict__ out, int N) {
    int n = blockIdx.x * 2 + (threadIdx.x >> 5);
    if (n >= N) return;
    int t = threadIdx.x & 31;
    const int2* edges = (const int2*)g_edges4;
    int e = __ldg(&rowptr[n]);
    int e1 = __ldg(&rowptr[n + 1]);
    float4 a01 = __ldg(&((const float4*)bias)[2 * t]);
    float4 a23 = __ldg(&((const float4*)bias)[2 * t + 1]);
    if (e < e1 && (e & 1)) {
        int2 ea = __ldg(&edges[e]);
        uint4 u = __ldg(&H[(size_t)ea.x * 32 + t]);
        float w = __int_as_float(ea.y);
        a01 = fma4_u2(a01, u.x, u.y, w);
        a23 = fma4_u2(a23, u.z, u.w, w);
        e++;
    }
    for (; e + 4 <= e1; e += 4) {
        int4 p = __ldg((const int4*)&edges[e]);
        int4 q = __ldg((const int4*)&edges[e + 2]);
        uint4 u0 = __ldg(&H[(size_t)p.x * 32 + t]);
        uint4 u1 = __ldg(&H[(size_t)p.z * 32 + t]);
        uint4 u2 = __ldg(&H[(size_t)q.x * 32 + t]);
        uint4 u3 = __ldg(&H[(size_t)q.z * 32 + t]);
        float w0 = __int_as_float(p.y), w1 = __int_as_float(p.w);
        float w2 = __int_as_float(q.y), w3 = __int_as_float(q.w);
        a01 = fma4_u2(a01, u0.x, u0.y, w0); a23 = fma4_u2(a23, u0.z, u0.w, w0);
        a01 = fma4_u2(a01, u1.x, u1.y, w1); a23 = fma4_u2(a23, u1.z, u1.w, w1);
        a01 = fma4_u2(a01, u2.x, u2.y, w2); a23 = fma4_u2(a23, u2.z, u2.w, w2);
        a01 = fma4_u2(a01, u3.x, u3.y, w3); a23 = fma4_u2(a23, u3.z, u3.w, w3);
    }
    for (; e < e1; e++) {
        int2 ea = __ldg(&edges[e]);
        uint4 u = __ldg(&H[(size_t)ea.x * 32 + t]);
        float w = __int_as_float(ea.y);
        a01 = fma4_u2(a01, u.x, u.y, w);
        a23 = fma4_u2(a23, u.z, u.w, w);
    }
    ((float4*)out)[(size_t)n * 64 + 2 * t] = a01;
    ((float4*)out)[(size_t)n * 64 + 2 * t + 1] = a23;
    // LN stats: warp shfl reduce
    double s = (double)a01.x + a01.y + a01.z + a01.w +
               (double)a23.x + a23.y + a23.z + a23.w;
    double q = (double)a01.x * a01.x + (double)a01.y * a01.y +
               (double)a01.z * a01.z + (double)a01.w * a01.w +
               (double)a23.x * a23.x + (double)a23.y * a23.y +
               (double)a23.z * a23.z + (double)a23.w * a23.w;
    for (int o = 16; o > 0; o >>= 1) {
        s += __shfl_xor_sync(0xFFFFFFFFu, s, o);
        q += __shfl_xor_sync(0xFFFFFFFFu, q, o);
    }
    if (t == 0) {
        atomicAdd(&g_scal[2], s);
        atomicAdd(&g_scal[3], q);
    }
}

// ---- Big-tile GEMM with packed f32x2 FMA ----
// C_h16[M,256] = A[M,K] @ B + bias(row-vec). Tile 128x128, BK=16, 256 thr, 8x8 micro.
template<int K, bool HALF_A, bool EPI1>
__global__ __launch_bounds__(256) void k_gemm_big(const float* __restrict__ Af,
                                                  const __half* __restrict__ Ah,
                                                  const float* __restrict__ B,
                                                  const float* __restrict__ bias,
                                                  __half* __restrict__ C, int M) {
    __shared__ float sA[16 * 136];   // [k][m], stride 136
    __shared__ float sB[16 * 132];   // [k][n], stride 132
    __shared__ double sds[512];
    int tid = threadIdx.x;
    int tx = tid & 15, ty = tid >> 4;
    int m0 = blockIdx.y * 128, n0 = blockIdx.x * 128;

    unsigned long long acc[8][4];
#pragma unroll
    for (int i = 0; i < 8; i++)
#pragma unroll
        for (int j = 0; j < 4; j++) acc[i][j] = 0ull;

    for (int k0 = 0; k0 < K; k0 += 16) {
#pragma unroll
        for (int l = 0; l < 2; l++) {
            int f = l * 256 + tid;
            int row = f >> 2;
            int c4 = (f & 3) * 4;
            float v0, v1, v2, v3;
            if (m0 + row < M) {
                if (HALF_A) {
                    uint2 u = *(const uint2*)(Ah + (size_t)(m0 + row) * HDIM + k0 + c4);
                    float2 f0 = __half22float2(*(__half2*)&u.x);
                    float2 f1 = __half22float2(*(__half2*)&u.y);
                    v0 = f0.x; v1 = f0.y; v2 = f1.x; v3 = f1.y;
                } else {
                    float4 av = *(const float4*)(Af + (size_t)(m0 + row) * K + k0 + c4);
                    v0 = av.x; v1 = av.y; v2 = av.z; v3 = av.w;
                }
            } else {
                v0 = v1 = v2 = v3 = 0.f;
            }
            sA[(c4 + 0) * 136 + row] = v0;
            sA[(c4 + 1) * 136 + row] = v1;
            sA[(c4 + 2) * 136 + row] = v2;
            sA[(c4 + 3) * 136 + row] = v3;
        }
#pragma unroll
        for (int l = 0; l < 2; l++) {
            int f = l * 256 + tid;
            int row = f >> 5;
            int c4 = (f & 31) * 4;
            *(float4*)&sB[row * 132 + c4] =
                *(const float4*)(B + (size_t)(k0 + row) * HDIM + n0 + c4);
        }
        __syncthreads();
#pragma unroll
        for (int k = 0; k < 16; k++) {
            float4 ra0 = *(const float4*)&sA[k * 136 + ty * 8];
            float4 ra1 = *(const float4*)&sA[k * 136 + ty * 8 + 4];
            ulonglong2 b01 = *(const ulonglong2*)&sB[k * 132 + tx * 8];
            ulonglong2 b23 = *(const ulonglong2*)&sB[k * 132 + tx * 8 + 4];
            float am[8] = {ra0.x, ra0.y, ra0.z, ra0.w, ra1.x, ra1.y, ra1.z, ra1.w};
#pragma unroll
            for (int i = 0; i < 8; i++) {
                unsigned long long pa = pk2(am[i], am[i]);
                acc[i][0] = ffma2(pa, b01.x, acc[i][0]);
                acc[i][1] = ffma2(pa, b01.y, acc[i][1]);
                acc[i][2] = ffma2(pa, b23.x, acc[i][2]);
                acc[i][3] = ffma2(pa, b23.y, acc[i][3]);
            }
        }
        __syncthreads();
    }

    float bv[8];
#pragma unroll
    for (int j = 0; j < 4; j++) {
        float2 b2 = *(const float2*)(bias + n0 + tx * 8 + j * 2);
        bv[2 * j] = b2.x;
        bv[2 * j + 1] = b2.y;
    }
    float s = 0.f, q = 0.f;
#pragma unroll
    for (int i = 0; i < 8; i++) {
        int row = m0 + ty * 8 + i;
        if (row < M) {
            __half2* dst = (__half2*)(C + (size_t)row * HDIM + n0 + tx * 8);
#pragma unroll
            for (int j = 0; j < 4; j++) {
                float lo, hi;
                upk2(acc[i][j], lo, hi);
                lo += bv[2 * j];
                hi += bv[2 * j + 1];
                dst[j] = __floats2half2_rn(lo, hi);
                if (EPI1) {
                    s += lo + hi;
                    q += lo * lo + hi * hi;
                }
            }
        }
    }
    if (EPI1) {
        sds[tid] = (double)s;
        sds[256 + tid] = (double)q;
        __syncthreads();
        for (int o = 128; o > 0; o >>= 1) {
            if (tid < o) {
                sds[tid] += sds[tid + o];
                sds[256 + tid] += sds[256 + tid + o];
            }
            __syncthreads();
        }
        if (tid == 0) {
            atomicAdd(&g_scal[0], sds[0]);
            atomicAdd(&g_scal[1], sds[256]);
        }
    }
}

// Fold LN1 into W2: a_k = inv*ln1w_k; c_k = ln1b_k - mean*a_k; d = c @ W2.
__global__ __launch_bounds__(256) void k_prep(const float* __restrict__ lnw,
                                              const float* __restrict__ lnb,
                                              const float* __restrict__ W2, int M) {
    __shared__ float cs[HDIM];
    int t = threadIdx.x;
    double nn = (double)M * HDIM;
    double mm = g_scal[0] / nn;
    double var = g_scal[1] / nn - mm * mm;
    float mean = (float)mm;
    float inv = 1.f / ((float)sqrt(var) + EPS);
    float a = inv * lnw[t];
    float c = lnb[t] - mean * a;
    g_avec[t] = a;
    cs[t] = c;
    __syncthreads();
    float d = 0.f;
    for (int k = 0; k < HDIM; k++) d += cs[k] * W2[k * HDIM + t];
    g_dvec[t] = d;
}

// W2f[k][n] = a_k * W2[k][n]
__global__ __launch_bounds__(256) void k_scaleW(const float* __restrict__ W2,
                                                float* __restrict__ W2f) {
    int k = blockIdx.x, n = threadIdx.x;
    W2f[k * HDIM + n] = g_avec[k] * W2[k * HDIM + n];
}

// Final in-place graph LayerNorm on out (stats in g_scal[2,3]).
__global__ __launch_bounds__(256) void k_ln(float* __restrict__ x,
                                            const float* __restrict__ w,
                                            const float* __restrict__ b,
                                            int n4, int which) {
    int i = blockIdx.x * blockDim.x + threadIdx.x;
    if (i >= n4) return;
    double n = (double)n4 * 4.0;
    double m = g_scal[which] / n;
    double var = g_scal[which + 1] / n - m * m;
    float mean = (float)m;
    float inv = 1.f / ((float)sqrt(var) + EPS);
    float4 v = ((float4*)x)[i];
    int c4 = i & 63;
    float4 wv = ((const float4*)w)[c4];
    float4 bv = ((const float4*)b)[c4];
    v.x = (v.x - mean) * inv * wv.x + bv.x;
    v.y = (v.y - mean) * inv * wv.y + bv.y;
    v.z = (v.z - mean) * inv * wv.z + bv.z;
    v.w = (v.w - mean) * inv * wv.w + bv.w;
    ((float4*)x)[i] = v;
}

extern "C" void kernel_launch(void* const* d_in, const int* in_sizes, int n_in,
                              void* d_out, int out_size) {
    const float* x = (const float*)d_in[0];
    const int* ei[4] = {(const int*)d_in[1], (const int*)d_in[3],
                        (const int*)d_in[5], (const int*)d_in[7]};
    const float* ew[4] = {(const float*)d_in[2], (const float*)d_in[4],
                          (const float*)d_in[6], (const float*)d_in[8]};
    const float* W1 = (const float*)d_in[9];
    const float* b1 = (const float*)d_in[10];
    const float* W2 = (const float*)d_in[11];
    const float* b2 = (const float*)d_in[12];
    const float* ln1w = (const float*)d_in[13];
    const float* ln1b = (const float*)d_in[14];
    const float* ln2w = (const float*)d_in[15];
    const float* ln2b = (const float*)d_in[16];

    int N = in_sizes[0] / F_IN;
    int E = in_sizes[1] / 2;
    int n4 = N * (HDIM / 4);
    int n2 = N * F_IN / 2;

    __half *xh, *h1h, *h2h;
    float *agg, *W2f, *dvec;
    int *rowptr, *pos, *deg;
    cudaGetSymbolAddress((void**)&xh, g_xh);
    cudaGetSymbolAddress((void**)&h1h, g_h1h);
    cudaGetSymbolAddress((void**)&h2h, g_h2h);
    cudaGetSymbolAddress((void**)&agg, g_agg);
    cudaGetSymbolAddress((void**)&W2f, g_W2f);
    cudaGetSymbolAddress((void**)&dvec, g_dvec);
    cudaGetSymbolAddress((void**)&rowptr, g_rowptr);
    cudaGetSymbolAddress((void**)&pos, g_pos);
    cudaGetSymbolAddress((void**)&deg, g_deg);
    float* out = (float*)d_out;

    int initBlocks = (n4 + 255) / 256;
    int e4Blocks = (4 * E + 255) / 256;
    int scanB = (N + 1023) / 1024;
    dim3 gbig(HDIM / 128, (N + 127) / 128);

    // [0] convert x -> fp16, zero deg
    k_convert_zdeg<<<(n2 + 255) / 256, 256>>>(x, xh, n2, deg, N);
    // [1] histogram (all 4 relations)
    k_hist_all<<<e4Blocks, 256>>>(ei[0], ei[1], ei[2], ei[3], deg, E);
    // [2] scan phase 1 (+ zero LN stats)
    k_scan1z<<<scanB, 1024>>>(deg, rowptr, N);
    // [3] scan phase 2+3
    k_scan3b<<<scanB, 1024>>>(rowptr, pos, deg, N);
    // [4] CSR fill (all 4 relations)
    k_fill_all<<<e4Blocks, 256>>>(ei[0], ew[0], ei[1], ew[1], ei[2], ew[2],
                                  ei[3], ew[3], pos, E);
    // [5] layer-1 gather (PROFILED by ncu -s 5 -c 1)
    k_gather1<<<(N + 1) / 2, 64>>>((const uint2*)xh, rowptr, agg, N);
    // [6] GEMM1 + bias + LN1 stats, fp16 out
    k_gemm_big<F_IN, false, true><<<gbig, 256>>>(agg, nullptr, W1, b1, h1h, N);
    // [7][8] fold LN1 into W2
    k_prep<<<1, 256>>>(ln1w, ln1b, W2, N);
    k_scaleW<<<HDIM, 256>>>(W2, W2f);
    // [9] GEMM2 (LN1-folded) + d, fp16 out
    k_gemm_big<HDIM, true, false><<<gbig, 256>>>(nullptr, h1h, W2f, dvec, h2h, N);
    // [10] layer-2 gather + b2 + LN2 stats
    k_gather2<<<(N + 1) / 2, 64>>>((const uint4*)h2h, rowptr, b2, out, N);
    // [11] final LayerNorm
    k_ln<<<initBlocks, 256>>>(out, ln2w, ln2b, n4, 2);
}

// round 14
// speedup vs baseline: 3.2764x; 1.0077x over previous
#include <cuda_runtime.h>
#include <cuda_fp16.h>
#include <math.h>

#define HDIM 256
#define F_IN 128
#define NMAX 100000
#define EMAX 1600000
#define ETOT (4 * EMAX)
#define EPS 1e-5f

// Scratch (allocation-free rule: __device__ globals)
__device__ __half g_xh[(size_t)NMAX * F_IN];     // x in fp16 (gather-1 source)
__device__ __half g_aggh[(size_t)NMAX * F_IN];   // layer-1 aggregate fp16 (GEMM1 A)
__device__ __half g_h1h[(size_t)NMAX * HDIM];    // GEMM1 output fp16 (GEMM2 A)
__device__ __half g_h2h[(size_t)NMAX * HDIM];    // GEMM2 output fp16 (gather-2 source)
__device__ float  g_W2f[HDIM * HDIM];            // a_k * W2[k][n] (LN1 folded)
__device__ float  g_avec[HDIM];
__device__ float  g_dvec[HDIM];                  // c @ W2
__device__ int4   g_edges4[ETOT / 2];            // CSR payload, 16B-aligned
__device__ int    g_rowptr[NMAX + 1];
__device__ int    g_pos[NMAX];
__device__ int    g_deg[NMAX];
__device__ int    g_bsum[128];
__device__ double g_scal[4];                     // [sum, sumsq] x 2 layers

// ---- packed f32x2 helpers (B300: 2x fp32 FMA rate, PTX-only pattern) ----
__device__ __forceinline__ unsigned long long pk2(float x, float y) {
    unsigned long long r;
    asm("mov.b64 %0, {%1, %2};" : "=l"(r) : "f"(x), "f"(y));
    return r;
}
__device__ __forceinline__ void upk2(unsigned long long v, float& x, float& y) {
    asm("mov.b64 {%0, %1}, %2;" : "=f"(x), "=f"(y) : "l"(v));
}
__device__ __forceinline__ unsigned long long ffma2(unsigned long long a,
                                                    unsigned long long b,
                                                    unsigned long long c) {
    unsigned long long d;
    asm("fma.rn.f32x2 %0, %1, %2, %3;" : "=l"(d) : "l"(a), "l"(b), "l"(c));
    return d;
}

// Fused: float->half convert of x AND zero deg.
__global__ __launch_bounds__(256) void k_convert_zdeg(const float* __restrict__ in,
                                                      __half* __restrict__ out, int n2,
                                                      int* __restrict__ deg, int N) {
    int i = blockIdx.x * blockDim.x + threadIdx.x;
    if (i < n2) {
        float2 v = ((const float2*)in)[i];
        ((__half2*)out)[i] = __floats2half2_rn(v.x, v.y);
    }
    if (i < N) deg[i] = 0;
}

// Histogram over all 4 relations in one kernel.
__global__ __launch_bounds__(256) void k_hist_all(const int* __restrict__ e0,
                                                  const int* __restrict__ e1,
                                                  const int* __restrict__ e2,
                                                  const int* __restrict__ e3,
                                                  int* __restrict__ deg, int E) {
    int t = blockIdx.x * blockDim.x + threadIdx.x;
    const int* p;
    if (t < E) p = e0;
    else if (t < 2 * E) { p = e1; t -= E; }
    else if (t < 3 * E) { p = e2; t -= 2 * E; }
    else if (t < 4 * E) { p = e3; t -= 3 * E; }
    else return;
    atomicAdd(&deg[p[E + t]], 1);
}

// Scan phase 1 (+ zero g_scal).
__global__ __launch_bounds__(1024) void k_scan1z(const int* __restrict__ deg,
                                                 int* __restrict__ rowptr, int N) {
    __shared__ int sh[1024];
    int tid = threadIdx.x;
    if (blockIdx.x == 0 && tid < 4) g_scal[tid] = 0.0;
    int i = blockIdx.x * 1024 + tid;
    int v = (i < N) ? deg[i] : 0;
    sh[tid] = v;
    __syncthreads();
    for (int o = 1; o < 1024; o <<= 1) {
        int t = (tid >= o) ? sh[tid - o] : 0;
        __syncthreads();
        sh[tid] += t;
        __syncthreads();
    }
    if (i < N) rowptr[i] = sh[tid] - v;
    if (tid == 1023) g_bsum[blockIdx.x] = sh[1023];
}

// Scan phase 2+3 fused: each block reduces bsum[0..bid) itself.
__global__ __launch_bounds__(1024) void k_scan3b(int* __restrict__ rowptr,
                                                 int* __restrict__ pos,
                                                 const int* __restrict__ deg, int N) {
    __shared__ int sh[128];
    __shared__ int off;
    int tid = threadIdx.x;
    int bid = blockIdx.x;
    if (tid < 128) {
        int partial = 0;
        for (int j = tid; j < bid; j += 128) partial += g_bsum[j];
        sh[tid] = partial;
    }
    __syncthreads();
    if (tid == 0) {
        int s = 0;
        for (int j = 0; j < 128; j++) s += sh[j];
        off = s;
    }
    __syncthreads();
    int i = bid * 1024 + tid;
    if (i < N) {
        int r = rowptr[i] + off;
        rowptr[i] = r;
        pos[i] = r;
        if (i == N - 1) rowptr[N] = r + deg[i];
    }
}

// Fill CSR payload for all 4 relations in one kernel.
__global__ __launch_bounds__(256) void k_fill_all(const int* __restrict__ e0,
                                                  const float* __restrict__ w0,
                                                  const int* __restrict__ e1,
                                                  const float* __restrict__ w1,
                                                  const int* __restrict__ e2,
                                                  const float* __restrict__ w2,
                                                  const int* __restrict__ e3,
                                                  const float* __restrict__ w3,
                                                  int* __restrict__ pos, int E) {
    int t = blockIdx.x * blockDim.x + threadIdx.x;
    const int* p;
    const float* w;
    if (t < E) { p = e0; w = w0; }
    else if (t < 2 * E) { p = e1; w = w1; t -= E; }
    else if (t < 3 * E) { p = e2; w = w2; t -= 2 * E; }
    else if (t < 4 * E) { p = e3; w = w3; t -= 3 * E; }
    else return;
    int dst = p[E + t];
    int q = atomicAdd(&pos[dst], 1);
    ((int2*)g_edges4)[q] = make_int2(p[t], __float_as_int(w[t]));
}

__device__ __forceinline__ float4 fma4_u2(float4 acc, unsigned lo, unsigned hi, float w) {
    float2 f0 = __half22float2(*(__half2*)&lo);
    float2 f1 = __half22float2(*(__half2*)&hi);
    acc.x += w * f0.x; acc.y += w * f0.y;
    acc.z += w * f1.x; acc.w += w * f1.y;
    return acc;
}

// Layer-1 gather: aggh[n, 0:128] = fp16(sum_e w * xh[src]). 1 warp/node, 2/block.
__global__ __launch_bounds__(64) void k_gather1(const uint2* __restrict__ X,
                                                const int* __restrict__ rowptr,
                                                __half* __restrict__ aggh, int N) {
    int n = blockIdx.x * 2 + (threadIdx.x >> 5);
    if (n >= N) return;
    int t = threadIdx.x & 31;
    const int2* edges = (const int2*)g_edges4;
    int e = __ldg(&rowptr[n]);
    int e1 = __ldg(&rowptr[n + 1]);
    float4 acc = make_float4(0.f, 0.f, 0.f, 0.f);
    if (e < e1 && (e & 1)) {
        int2 ea = __ldg(&edges[e]);
        uint2 u = __ldg(&X[(size_t)ea.x * 32 + t]);
        acc = fma4_u2(acc, u.x, u.y, __int_as_float(ea.y));
        e++;
    }
    for (; e + 4 <= e1; e += 4) {
        int4 p = __ldg((const int4*)&edges[e]);
        int4 q = __ldg((const int4*)&edges[e + 2]);
        uint2 u0 = __ldg(&X[(size_t)p.x * 32 + t]);
        uint2 u1 = __ldg(&X[(size_t)p.z * 32 + t]);
        uint2 u2 = __ldg(&X[(size_t)q.x * 32 + t]);
        uint2 u3 = __ldg(&X[(size_t)q.z * 32 + t]);
        acc = fma4_u2(acc, u0.x, u0.y, __int_as_float(p.y));
        acc = fma4_u2(acc, u1.x, u1.y, __int_as_float(p.w));
        acc = fma4_u2(acc, u2.x, u2.y, __int_as_float(q.y));
        acc = fma4_u2(acc, u3.x, u3.y, __int_as_float(q.w));
    }
    for (; e < e1; e++) {
        int2 ea = __ldg(&edges[e]);
        uint2 u = __ldg(&X[(size_t)ea.x * 32 + t]);
        acc = fma4_u2(acc, u.x, u.y, __int_as_float(ea.y));
    }
    __half2 h0 = __floats2half2_rn(acc.x, acc.y);
    __half2 h1 = __floats2half2_rn(acc.z, acc.w);
    uint2 pk;
    pk.x = *(unsigned*)&h0;
    pk.y = *(unsigned*)&h1;
    *(uint2*)(aggh + (size_t)n * F_IN + 4 * t) = pk;
}

// Layer-2 gather: out[n, 0:256] = b2 + sum_e w * h2h[src]; + LN stats -> g_scal[2,3].
__global__ __launch_bounds__(64) void k_gather2(const uint4* __restrict__ H,
                                                const int* __restrict__ rowptr,
                                                const float* __restrict__ bias,
                                                float* __restrict__ out, int N) {
    int n = blockIdx.x * 2 + (threadIdx.x >> 5);
    if (n >= N) return;
    int t = threadIdx.x & 31;
    const int2* edges = (const int2*)g_edges4;
    int e = __ldg(&rowptr[n]);
    int e1 = __ldg(&rowptr[n + 1]);
    float4 a01 = __ldg(&((const float4*)bias)[2 * t]);
    float4 a23 = __ldg(&((const float4*)bias)[2 * t + 1]);
    if (e < e1 && (e & 1)) {
        int2 ea = __ldg(&edges[e]);
        uint4 u = __ldg(&H[(size_t)ea.x * 32 + t]);
        float w = __int_as_float(ea.y);
        a01 = fma4_u2(a01, u.x, u.y, w);
        a23 = fma4_u2(a23, u.z, u.w, w);
        e++;
    }
    for (; e + 4 <= e1; e += 4) {
        int4 p = __ldg((const int4*)&edges[e]);
        int4 q = __ldg((const int4*)&edges[e + 2]);
        uint4 u0 = __ldg(&H[(size_t)p.x * 32 + t]);
        uint4 u1 = __ldg(&H[(size_t)p.z * 32 + t]);
        uint4 u2 = __ldg(&H[(size_t)q.x * 32 + t]);
        uint4 u3 = __ldg(&H[(size_t)q.z * 32 + t]);
        float w0 = __int_as_float(p.y), w1 = __int_as_float(p.w);
        float w2 = __int_as_float(q.y), w3 = __int_as_float(q.w);
        a01 = fma4_u2(a01, u0.x, u0.y, w0); a23 = fma4_u2(a23, u0.z, u0.w, w0);
        a01 = fma4_u2(a01, u1.x, u1.y, w1); a23 = fma4_u2(a23, u1.z, u1.w, w1);
        a01 = fma4_u2(a01, u2.x, u2.y, w2); a23 = fma4_u2(a23, u2.z, u2.w, w2);
        a01 = fma4_u2(a01, u3.x, u3.y, w3); a23 = fma4_u2(a23, u3.z, u3.w, w3);
    }
    for (; e < e1; e++) {
        int2 ea = __ldg(&edges[e]);
        uint4 u = __ldg(&H[(size_t)ea.x * 32 + t]);
        float w = __int_as_float(ea.y);
        a01 = fma4_u2(a01, u.x, u.y, w);
        a23 = fma4_u2(a23, u.z, u.w, w);
    }
    ((float4*)out)[(size_t)n * 64 + 2 * t] = a01;
    ((float4*)out)[(size_t)n * 64 + 2 * t + 1] = a23;
    double s = (double)a01.x + a01.y + a01.z + a01.w +
               (double)a23.x + a23.y + a23.z + a23.w;
    double q = (double)a01.x * a01.x + (double)a01.y * a01.y +
               (double)a01.z * a01.z + (double)a01.w * a01.w +
               (double)a23.x * a23.x + (double)a23.y * a23.y +
               (double)a23.z * a23.z + (double)a23.w * a23.w;
    for (int o = 16; o > 0; o >>= 1) {
        s += __shfl_xor_sync(0xFFFFFFFFu, s, o);
        q += __shfl_xor_sync(0xFFFFFFFFu, q, o);
    }
    if (t == 0) {
        atomicAdd(&g_scal[2], s);
        atomicAdd(&g_scal[3], q);
    }
}

// ---- Big-tile GEMM, fp16 A, double-buffered SMEM, packed f32x2 FMA ----
// C_h16[M,256] = A_h16[M,K(stride ASTR)] @ B + bias(row-vec). Tile 128x128, BK=16.
template<int K, int ASTR, bool EPI1>
__global__ __launch_bounds__(256) void k_gemm_big(const __half* __restrict__ Ah,
                                                  const float* __restrict__ B,
                                                  const float* __restrict__ bias,
                                                  __half* __restrict__ C, int M) {
    __shared__ float sA[2][16 * 136];   // [k][m]
    __shared__ float sB[2][16 * 132];   // [k][n]
    __shared__ double sds[512];
    const int NT = K / 16;
    int tid = threadIdx.x;
    int tx = tid & 15, ty = tid >> 4;
    int m0 = blockIdx.y * 128, n0 = blockIdx.x * 128;

    unsigned long long acc[8][4];
#pragma unroll
    for (int i = 0; i < 8; i++)
#pragma unroll
        for (int j = 0; j < 4; j++) acc[i][j] = 0ull;

    // Per-thread tile-load coordinates
    int fa0 = tid, fa1 = 256 + tid;
    int ar0 = fa0 >> 2, ac0 = (fa0 & 3) * 4;
    int ar1 = fa1 >> 2, ac1 = (fa1 & 3) * 4;
    int br0 = (tid) >> 5, bc0 = (tid & 31) * 4;
    int br1 = (256 + tid) >> 5, bc1 = ((256 + tid) & 31) * 4;

    uint2 aL0, aL1;
    float4 bL0, bL1;
    auto loadg = [&](int k0) {
        aL0 = (m0 + ar0 < M)
                  ? *(const uint2*)(Ah + (size_t)(m0 + ar0) * ASTR + k0 + ac0)
                  : make_uint2(0u, 0u);
        aL1 = (m0 + ar1 < M)
                  ? *(const uint2*)(Ah + (size_t)(m0 + ar1) * ASTR + k0 + ac1)
                  : make_uint2(0u, 0u);
        bL0 = *(const float4*)(B + (size_t)(k0 + br0) * HDIM + n0 + bc0);
        bL1 = *(const float4*)(B + (size_t)(k0 + br1) * HDIM + n0 + bc1);
    };
    auto store_s = [&](int buf) {
        float2 f0 = __half22float2(*(__half2*)&aL0.x);
        float2 f1 = __half22float2(*(__half2*)&aL0.y);
        sA[buf][(ac0 + 0) * 136 + ar0] = f0.x;
        sA[buf][(ac0 + 1) * 136 + ar0] = f0.y;
        sA[buf][(ac0 + 2) * 136 + ar0] = f1.x;
        sA[buf][(ac0 + 3) * 136 + ar0] = f1.y;
        float2 f2 = __half22float2(*(__half2*)&aL1.x);
        float2 f3 = __half22float2(*(__half2*)&aL1.y);
        sA[buf][(ac1 + 0) * 136 + ar1] = f2.x;
        sA[buf][(ac1 + 1) * 136 + ar1] = f2.y;
        sA[buf][(ac1 + 2) * 136 + ar1] = f3.x;
        sA[buf][(ac1 + 3) * 136 + ar1] = f3.y;
        *(float4*)&sB[buf][br0 * 132 + bc0] = bL0;
        *(float4*)&sB[buf][br1 * 132 + bc1] = bL1;
    };

    loadg(0);
    store_s(0);
    __syncthreads();
    int buf = 0;
    for (int kt = 0; kt < NT; kt++) {
        if (kt + 1 < NT) loadg((kt + 1) * 16);
#pragma unroll
        for (int k = 0; k < 16; k++) {
            float4 ra0 = *(const float4*)&sA[buf][k * 136 + ty * 8];
            float4 ra1 = *(const float4*)&sA[buf][k * 136 + ty * 8 + 4];
            ulonglong2 b01 = *(const ulonglong2*)&sB[buf][k * 132 + tx * 8];
            ulonglong2 b23 = *(const ulonglong2*)&sB[buf][k * 132 + tx * 8 + 4];
            float am[8] = {ra0.x, ra0.y, ra0.z, ra0.w, ra1.x, ra1.y, ra1.z, ra1.w};
#pragma unroll
            for (int i = 0; i < 8; i++) {
                unsigned long long pa = pk2(am[i], am[i]);
                acc[i][0] = ffma2(pa, b01.x, acc[i][0]);
                acc[i][1] = ffma2(pa, b01.y, acc[i][1]);
                acc[i][2] = ffma2(pa, b23.x, acc[i][2]);
                acc[i][3] = ffma2(pa, b23.y, acc[i][3]);
            }
        }
        if (kt + 1 < NT) {
            store_s(buf ^ 1);
            __syncthreads();
            buf ^= 1;
        }
    }

    float bv[8];
#pragma unroll
    for (int j = 0; j < 4; j++) {
        float2 b2 = *(const float2*)(bias + n0 + tx * 8 + j * 2);
        bv[2 * j] = b2.x;
        bv[2 * j + 1] = b2.y;
    }
    float s = 0.f, q = 0.f;
#pragma unroll
    for (int i = 0; i < 8; i++) {
        int row = m0 + ty * 8 + i;
        if (row < M) {
            __half2* dst = (__half2*)(C + (size_t)row * HDIM + n0 + tx * 8);
#pragma unroll
            for (int j = 0; j < 4; j++) {
                float lo, hi;
                upk2(acc[i][j], lo, hi);
                lo += bv[2 * j];
                hi += bv[2 * j + 1];
                dst[j] = __floats2half2_rn(lo, hi);
                if (EPI1) {
                    s += lo + hi;
                    q += lo * lo + hi * hi;
                }
            }
        }
    }
    if (EPI1) {
        sds[tid] = (double)s;
        sds[256 + tid] = (double)q;
        __syncthreads();
        for (int o = 128; o > 0; o >>= 1) {
            if (tid < o) {
                sds[tid] += sds[tid + o];
                sds[256 + tid] += sds[256 + tid + o];
            }
            __syncthreads();
        }
        if (tid == 0) {
            atomicAdd(&g_scal[0], sds[0]);
            atomicAdd(&g_scal[1], sds[256]);
        }
    }
}

// Fold LN1 into W2: a_k = inv*ln1w_k; c_k = ln1b_k - mean*a_k; d = c @ W2.
__global__ __launch_bounds__(256) void k_prep(const float* __restrict__ lnw,
                                              const float* __restrict__ lnb,
                                              const float* __restrict__ W2, int M) {
    __shared__ float cs[HDIM];
    int t = threadIdx.x;
    double nn = (double)M * HDIM;
    double mm = g_scal[0] / nn;
    double var = g_scal[1] / nn - mm * mm;
    float mean = (float)mm;
    float inv = 1.f / ((float)sqrt(var) + EPS);
    float a = inv * lnw[t];
    float c = lnb[t] - mean * a;
    g_avec[t] = a;
    cs[t] = c;
    __syncthreads();
    float d = 0.f;
    for (int k = 0; k < HDIM; k++) d += cs[k] * W2[k * HDIM + t];
    g_dvec[t] = d;
}

// W2f[k][n] = a_k * W2[k][n]
__global__ __launch_bounds__(256) void k_scaleW(const float* __restrict__ W2,
                                                float* __restrict__ W2f) {
    int k = blockIdx.x, n = threadIdx.x;
    W2f[k * HDIM + n] = g_avec[k] * W2[k * HDIM + n];
}

// Final in-place graph LayerNorm on out (stats in g_scal[2,3]).
__global__ __launch_bounds__(256) void k_ln(float* __restrict__ x,
                                            const float* __restrict__ w,
                                            const float* __restrict__ b,
                                            int n4, int which) {
    int i = blockIdx.x * blockDim.x + threadIdx.x;
    if (i >= n4) return;
    double n = (double)n4 * 4.0;
    double m = g_scal[which] / n;
    double var = g_scal[which + 1] / n - m * m;
    float mean = (float)m;
    float inv = 1.f / ((float)sqrt(var) + EPS);
    float4 v = ((float4*)x)[i];
    int c4 = i & 63;
    float4 wv = ((const float4*)w)[c4];
    float4 bv = ((const float4*)b)[c4];
    v.x = (v.x - mean) * inv * wv.x + bv.x;
    v.y = (v.y - mean) * inv * wv.y + bv.y;
    v.z = (v.z - mean) * inv * wv.z + bv.z;
    v.w = (v.w - mean) * inv * wv.w + bv.w;
    ((float4*)x)[i] = v;
}

extern "C" void kernel_launch(void* const* d_in, const int* in_sizes, int n_in,
                              void* d_out, int out_size) {
    const float* x = (const float*)d_in[0];
    const int* ei[4] = {(const int*)d_in[1], (const int*)d_in[3],
                        (const int*)d_in[5], (const int*)d_in[7]};
    const float* ew[4] = {(const float*)d_in[2], (const float*)d_in[4],
                          (const float*)d_in[6], (const float*)d_in[8]};
    const float* W1 = (const float*)d_in[9];
    const float* b1 = (const float*)d_in[10];
    const float* W2 = (const float*)d_in[11];
    const float* b2 = (const float*)d_in[12];
    const float* ln1w = (const float*)d_in[13];
    const float* ln1b = (const float*)d_in[14];
    const float* ln2w = (const float*)d_in[15];
    const float* ln2b = (const float*)d_in[16];

    int N = in_sizes[0] / F_IN;
    int E = in_sizes[1] / 2;
    int n4 = N * (HDIM / 4);
    int n2 = N * F_IN / 2;

    __half *xh, *aggh, *h1h, *h2h;
    float *W2f, *dvec;
    int *rowptr, *pos, *deg;
    cudaGetSymbolAddress((void**)&xh, g_xh);
    cudaGetSymbolAddress((void**)&aggh, g_aggh);
    cudaGetSymbolAddress((void**)&h1h, g_h1h);
    cudaGetSymbolAddress((void**)&h2h, g_h2h);
    cudaGetSymbolAddress((void**)&W2f, g_W2f);
    cudaGetSymbolAddress((void**)&dvec, g_dvec);
    cudaGetSymbolAddress((void**)&rowptr, g_rowptr);
    cudaGetSymbolAddress((void**)&pos, g_pos);
    cudaGetSymbolAddress((void**)&deg, g_deg);
    float* out = (float*)d_out;

    int initBlocks = (n4 + 255) / 256;
    int e4Blocks = (4 * E + 255) / 256;
    int scanB = (N + 1023) / 1024;
    dim3 gbig(HDIM / 128, (N + 127) / 128);

    k_convert_zdeg<<<(n2 + 255) / 256, 256>>>(x, xh, n2, deg, N);
    k_hist_all<<<e4Blocks, 256>>>(ei[0], ei[1], ei[2], ei[3], deg, E);
    k_scan1z<<<scanB, 1024>>>(deg, rowptr, N);
    k_scan3b<<<scanB, 1024>>>(rowptr, pos, deg, N);
    k_fill_all<<<e4Blocks, 256>>>(ei[0], ew[0], ei[1], ew[1], ei[2], ew[2],
                                  ei[3], ew[3], pos, E);
    k_gather1<<<(N + 1) / 2, 64>>>((const uint2*)xh, rowptr, aggh, N);
    k_gemm_big<F_IN, F_IN, true><<<gbig, 256>>>(aggh, W1, b1, h1h, N);
    k_prep<<<1, 256>>>(ln1w, ln1b, W2, N);
    k_scaleW<<<HDIM, 256>>>(W2, W2f);
    k_gemm_big<HDIM, HDIM, false><<<gbig, 256>>>(h1h, W2f, dvec, h2h, N);
    k_gather2<<<(N + 1) / 2, 64>>>((const uint4*)h2h, rowptr, b2, out, N);
    k_ln<<<initBlocks, 256>>>(out, ln2w, ln2b, n4, 2);
}

// round 15
// speedup vs baseline: 3.7101x; 1.1324x over previous
#include <cuda_runtime.h>
#include <cuda_fp16.h>
#include <math.h>

#define HDIM 256
#define F_IN 128
#define NMAX 100000
#define EMAX 1600000
#define ETOT (4 * EMAX)
#define EPS 1e-5f

// Scratch (allocation-free rule: __device__ globals)
__device__ __half g_xh[(size_t)NMAX * F_IN];     // x in fp16 (gather-1 source)
__device__ __half g_aggh[(size_t)NMAX * F_IN];   // layer-1 aggregate fp16 (GEMM1 A)
__device__ __half g_h1h[(size_t)NMAX * HDIM];    // GEMM1 output fp16 (GEMM2 A)
__device__ __half g_h2h[(size_t)NMAX * HDIM];    // GEMM2 output fp16 (gather-2 source)
__device__ __half g_hout[(size_t)NMAX * HDIM];   // gather-2 output fp16 (pre-LN2)
__device__ float  g_W2f[HDIM * HDIM];            // a_k * W2[k][n] (LN1 folded)
__device__ float  g_avec[HDIM];
__device__ float  g_dvec[HDIM];                  // c @ W2
__device__ int4   g_edges4[ETOT / 2];            // CSR payload, 16B-aligned
__device__ int    g_rowptr[NMAX + 1];
__device__ int    g_pos[NMAX];
__device__ int    g_deg[NMAX];
__device__ int    g_bsum[128];
__device__ double g_scal[4];                     // [sum, sumsq] x 2 layers

// ---- packed f32x2 helpers (B300: 2x fp32 FMA rate, PTX-only pattern) ----
__device__ __forceinline__ unsigned long long pk2(float x, float y) {
    unsigned long long r;
    asm("mov.b64 %0, {%1, %2};" : "=l"(r) : "f"(x), "f"(y));
    return r;
}
__device__ __forceinline__ void upk2(unsigned long long v, float& x, float& y) {
    asm("mov.b64 {%0, %1}, %2;" : "=f"(x), "=f"(y) : "l"(v));
}
__device__ __forceinline__ unsigned long long ffma2(unsigned long long a,
                                                    unsigned long long b,
                                                    unsigned long long c) {
    unsigned long long d;
    asm("fma.rn.f32x2 %0, %1, %2, %3;" : "=l"(d) : "l"(a), "l"(b), "l"(c));
    return d;
}

// Fused: float->half convert of x AND zero deg.
__global__ __launch_bounds__(256) void k_convert_zdeg(const float* __restrict__ in,
                                                      __half* __restrict__ out, int n2,
                                                      int* __restrict__ deg, int N) {
    int i = blockIdx.x * blockDim.x + threadIdx.x;
    if (i < n2) {
        float2 v = __ldcs(&((const float2*)in)[i]);
        ((__half2*)out)[i] = __floats2half2_rn(v.x, v.y);
    }
    if (i < N) deg[i] = 0;
}

// Histogram over all 4 relations in one kernel.
__global__ __launch_bounds__(256) void k_hist_all(const int* __restrict__ e0,
                                                  const int* __restrict__ e1,
                                                  const int* __restrict__ e2,
                                                  const int* __restrict__ e3,
                                                  int* __restrict__ deg, int E) {
    int t = blockIdx.x * blockDim.x + threadIdx.x;
    const int* p;
    if (t < E) p = e0;
    else if (t < 2 * E) { p = e1; t -= E; }
    else if (t < 3 * E) { p = e2; t -= 2 * E; }
    else if (t < 4 * E) { p = e3; t -= 3 * E; }
    else return;
    atomicAdd(&deg[__ldcs(&p[E + t])], 1);
}

// Scan phase 1 (+ zero g_scal).
__global__ __launch_bounds__(1024) void k_scan1z(const int* __restrict__ deg,
                                                 int* __restrict__ rowptr, int N) {
    __shared__ int sh[1024];
    int tid = threadIdx.x;
    if (blockIdx.x == 0 && tid < 4) g_scal[tid] = 0.0;
    int i = blockIdx.x * 1024 + tid;
    int v = (i < N) ? deg[i] : 0;
    sh[tid] = v;
    __syncthreads();
    for (int o = 1; o < 1024; o <<= 1) {
        int t = (tid >= o) ? sh[tid - o] : 0;
        __syncthreads();
        sh[tid] += t;
        __syncthreads();
    }
    if (i < N) rowptr[i] = sh[tid] - v;
    if (tid == 1023) g_bsum[blockIdx.x] = sh[1023];
}

// Scan phase 2+3 fused: each block reduces bsum[0..bid) itself.
__global__ __launch_bounds__(1024) void k_scan3b(int* __restrict__ rowptr,
                                                 int* __restrict__ pos,
                                                 const int* __restrict__ deg, int N) {
    __shared__ int sh[128];
    __shared__ int off;
    int tid = threadIdx.x;
    int bid = blockIdx.x;
    if (tid < 128) {
        int partial = 0;
        for (int j = tid; j < bid; j += 128) partial += g_bsum[j];
        sh[tid] = partial;
    }
    __syncthreads();
    if (tid == 0) {
        int s = 0;
        for (int j = 0; j < 128; j++) s += sh[j];
        off = s;
    }
    __syncthreads();
    int i = bid * 1024 + tid;
    if (i < N) {
        int r = rowptr[i] + off;
        rowptr[i] = r;
        pos[i] = r;
        if (i == N - 1) rowptr[N] = r + deg[i];
    }
}

// Fill CSR payload for all 4 relations in one kernel.
__global__ __launch_bounds__(256) void k_fill_all(const int* __restrict__ e0,
                                                  const float* __restrict__ w0,
                                                  const int* __restrict__ e1,
                                                  const float* __restrict__ w1,
                                                  const int* __restrict__ e2,
                                                  const float* __restrict__ w2,
                                                  const int* __restrict__ e3,
                                                  const float* __restrict__ w3,
                                                  int* __restrict__ pos, int E) {
    int t = blockIdx.x * blockDim.x + threadIdx.x;
    const int* p;
    const float* w;
    if (t < E) { p = e0; w = w0; }
    else if (t < 2 * E) { p = e1; w = w1; t -= E; }
    else if (t < 3 * E) { p = e2; w = w2; t -= 2 * E; }
    else if (t < 4 * E) { p = e3; w = w3; t -= 3 * E; }
    else return;
    int dst = __ldcs(&p[E + t]);
    int q = atomicAdd(&pos[dst], 1);
    ((int2*)g_edges4)[q] = make_int2(__ldcs(&p[t]), __float_as_int(__ldcs(&w[t])));
}

__device__ __forceinline__ float4 fma4_u2(float4 acc, unsigned lo, unsigned hi, float w) {
    float2 f0 = __half22float2(*(__half2*)&lo);
    float2 f1 = __half22float2(*(__half2*)&hi);
    acc.x += w * f0.x; acc.y += w * f0.y;
    acc.z += w * f1.x; acc.w += w * f1.y;
    return acc;
}

// Layer-1 gather: aggh[n, 0:128] = fp16(sum_e w * xh[src]). 1 warp/node, 2/block.
__global__ __launch_bounds__(64) void k_gather1(const uint2* __restrict__ X,
                                                const int* __restrict__ rowptr,
                                                __half* __restrict__ aggh, int N) {
    int n = blockIdx.x * 2 + (threadIdx.x >> 5);
    if (n >= N) return;
    int t = threadIdx.x & 31;
    const int2* edges = (const int2*)g_edges4;
    int e = __ldg(&rowptr[n]);
    int e1 = __ldg(&rowptr[n + 1]);
    float4 acc = make_float4(0.f, 0.f, 0.f, 0.f);
    if (e < e1 && (e & 1)) {
        int2 ea = __ldcs(&edges[e]);
        uint2 u = __ldg(&X[(size_t)ea.x * 32 + t]);
        acc = fma4_u2(acc, u.x, u.y, __int_as_float(ea.y));
        e++;
    }
    for (; e + 4 <= e1; e += 4) {
        int4 p = __ldcs((const int4*)&edges[e]);
        int4 q = __ldcs((const int4*)&edges[e + 2]);
        uint2 u0 = __ldg(&X[(size_t)p.x * 32 + t]);
        uint2 u1 = __ldg(&X[(size_t)p.z * 32 + t]);
        uint2 u2 = __ldg(&X[(size_t)q.x * 32 + t]);
        uint2 u3 = __ldg(&X[(size_t)q.z * 32 + t]);
        acc = fma4_u2(acc, u0.x, u0.y, __int_as_float(p.y));
        acc = fma4_u2(acc, u1.x, u1.y, __int_as_float(p.w));
        acc = fma4_u2(acc, u2.x, u2.y, __int_as_float(q.y));
        acc = fma4_u2(acc, u3.x, u3.y, __int_as_float(q.w));
    }
    for (; e < e1; e++) {
        int2 ea = __ldcs(&edges[e]);
        uint2 u = __ldg(&X[(size_t)ea.x * 32 + t]);
        acc = fma4_u2(acc, u.x, u.y, __int_as_float(ea.y));
    }
    __half2 h0 = __floats2half2_rn(acc.x, acc.y);
    __half2 h1 = __floats2half2_rn(acc.z, acc.w);
    uint2 pk;
    pk.x = *(unsigned*)&h0;
    pk.y = *(unsigned*)&h1;
    __stcs((uint2*)(aggh + (size_t)n * F_IN + 4 * t), pk);
}

// Layer-2 gather: hout[n] = fp16(b2 + sum_e w * h2h[src]); LN stats -> g_scal[2,3].
__global__ __launch_bounds__(64) void k_gather2(const uint4* __restrict__ H,
                                                const int* __restrict__ rowptr,
                                                const float* __restrict__ bias,
                                                __half* __restrict__ hout, int N) {
    int n = blockIdx.x * 2 + (threadIdx.x >> 5);
    if (n >= N) return;
    int t = threadIdx.x & 31;
    const int2* edges = (const int2*)g_edges4;
    int e = __ldg(&rowptr[n]);
    int e1 = __ldg(&rowptr[n + 1]);
    float4 a01 = __ldg(&((const float4*)bias)[2 * t]);
    float4 a23 = __ldg(&((const float4*)bias)[2 * t + 1]);
    if (e < e1 && (e & 1)) {
        int2 ea = __ldcs(&edges[e]);
        uint4 u = __ldg(&H[(size_t)ea.x * 32 + t]);
        float w = __int_as_float(ea.y);
        a01 = fma4_u2(a01, u.x, u.y, w);
        a23 = fma4_u2(a23, u.z, u.w, w);
        e++;
    }
    for (; e + 4 <= e1; e += 4) {
        int4 p = __ldcs((const int4*)&edges[e]);
        int4 q = __ldcs((const int4*)&edges[e + 2]);
        uint4 u0 = __ldg(&H[(size_t)p.x * 32 + t]);
        uint4 u1 = __ldg(&H[(size_t)p.z * 32 + t]);
        uint4 u2 = __ldg(&H[(size_t)q.x * 32 + t]);
        uint4 u3 = __ldg(&H[(size_t)q.z * 32 + t]);
        float w0 = __int_as_float(p.y), w1 = __int_as_float(p.w);
        float w2 = __int_as_float(q.y), w3 = __int_as_float(q.w);
        a01 = fma4_u2(a01, u0.x, u0.y, w0); a23 = fma4_u2(a23, u0.z, u0.w, w0);
        a01 = fma4_u2(a01, u1.x, u1.y, w1); a23 = fma4_u2(a23, u1.z, u1.w, w1);
        a01 = fma4_u2(a01, u2.x, u2.y, w2); a23 = fma4_u2(a23, u2.z, u2.w, w2);
        a01 = fma4_u2(a01, u3.x, u3.y, w3); a23 = fma4_u2(a23, u3.z, u3.w, w3);
    }
    for (; e < e1; e++) {
        int2 ea = __ldcs(&edges[e]);
        uint4 u = __ldg(&H[(size_t)ea.x * 32 + t]);
        float w = __int_as_float(ea.y);
        a01 = fma4_u2(a01, u.x, u.y, w);
        a23 = fma4_u2(a23, u.z, u.w, w);
    }
    // fp16 store (evict-first)
    __half2 h0 = __floats2half2_rn(a01.x, a01.y);
    __half2 h1 = __floats2half2_rn(a01.z, a01.w);
    __half2 h2 = __floats2half2_rn(a23.x, a23.y);
    __half2 h3 = __floats2half2_rn(a23.z, a23.w);
    uint4 pk;
    pk.x = *(unsigned*)&h0; pk.y = *(unsigned*)&h1;
    pk.z = *(unsigned*)&h2; pk.w = *(unsigned*)&h3;
    __stcs((uint4*)(hout + (size_t)n * HDIM) + t, pk);
    // LN stats from fp32 accumulators
    double s = (double)a01.x + a01.y + a01.z + a01.w +
               (double)a23.x + a23.y + a23.z + a23.w;
    double q = (double)a01.x * a01.x + (double)a01.y * a01.y +
               (double)a01.z * a01.z + (double)a01.w * a01.w +
               (double)a23.x * a23.x + (double)a23.y * a23.y +
               (double)a23.z * a23.z + (double)a23.w * a23.w;
    for (int o = 16; o > 0; o >>= 1) {
        s += __shfl_xor_sync(0xFFFFFFFFu, s, o);
        q += __shfl_xor_sync(0xFFFFFFFFu, q, o);
    }
    if (t == 0) {
        atomicAdd(&g_scal[2], s);
        atomicAdd(&g_scal[3], q);
    }
}

// ---- Big-tile GEMM, fp16 A, double-buffered SMEM, packed f32x2 FMA ----
template<int K, int ASTR, bool EPI1>
__global__ __launch_bounds__(256) void k_gemm_big(const __half* __restrict__ Ah,
                                                  const float* __restrict__ B,
                                                  const float* __restrict__ bias,
                                                  __half* __restrict__ C, int M) {
    __shared__ float sA[2][16 * 136];
    __shared__ float sB[2][16 * 132];
    __shared__ double sds[512];
    const int NT = K / 16;
    int tid = threadIdx.x;
    int tx = tid & 15, ty = tid >> 4;
    int m0 = blockIdx.y * 128, n0 = blockIdx.x * 128;

    unsigned long long acc[8][4];
#pragma unroll
    for (int i = 0; i < 8; i++)
#pragma unroll
        for (int j = 0; j < 4; j++) acc[i][j] = 0ull;

    int fa0 = tid, fa1 = 256 + tid;
    int ar0 = fa0 >> 2, ac0 = (fa0 & 3) * 4;
    int ar1 = fa1 >> 2, ac1 = (fa1 & 3) * 4;
    int br0 = (tid) >> 5, bc0 = (tid & 31) * 4;
    int br1 = (256 + tid) >> 5, bc1 = ((256 + tid) & 31) * 4;

    uint2 aL0, aL1;
    float4 bL0, bL1;
    auto loadg = [&](int k0) {
        aL0 = (m0 + ar0 < M)
                  ? *(const uint2*)(Ah + (size_t)(m0 + ar0) * ASTR + k0 + ac0)
                  : make_uint2(0u, 0u);
        aL1 = (m0 + ar1 < M)
                  ? *(const uint2*)(Ah + (size_t)(m0 + ar1) * ASTR + k0 + ac1)
                  : make_uint2(0u, 0u);
        bL0 = *(const float4*)(B + (size_t)(k0 + br0) * HDIM + n0 + bc0);
        bL1 = *(const float4*)(B + (size_t)(k0 + br1) * HDIM + n0 + bc1);
    };
    auto store_s = [&](int buf) {
        float2 f0 = __half22float2(*(__half2*)&aL0.x);
        float2 f1 = __half22float2(*(__half2*)&aL0.y);
        sA[buf][(ac0 + 0) * 136 + ar0] = f0.x;
        sA[buf][(ac0 + 1) * 136 + ar0] = f0.y;
        sA[buf][(ac0 + 2) * 136 + ar0] = f1.x;
        sA[buf][(ac0 + 3) * 136 + ar0] = f1.y;
        float2 f2 = __half22float2(*(__half2*)&aL1.x);
        float2 f3 = __half22float2(*(__half2*)&aL1.y);
        sA[buf][(ac1 + 0) * 136 + ar1] = f2.x;
        sA[buf][(ac1 + 1) * 136 + ar1] = f2.y;
        sA[buf][(ac1 + 2) * 136 + ar1] = f3.x;
        sA[buf][(ac1 + 3) * 136 + ar1] = f3.y;
        *(float4*)&sB[buf][br0 * 132 + bc0] = bL0;
        *(float4*)&sB[buf][br1 * 132 + bc1] = bL1;
    };

    loadg(0);
    store_s(0);
    __syncthreads();
    int buf = 0;
    for (int kt = 0; kt < NT; kt++) {
        if (kt + 1 < NT) loadg((kt + 1) * 16);
#pragma unroll
        for (int k = 0; k < 16; k++) {
            float4 ra0 = *(const float4*)&sA[buf][k * 136 + ty * 8];
            float4 ra1 = *(const float4*)&sA[buf][k * 136 + ty * 8 + 4];
            ulonglong2 b01 = *(const ulonglong2*)&sB[buf][k * 132 + tx * 8];
            ulonglong2 b23 = *(const ulonglong2*)&sB[buf][k * 132 + tx * 8 + 4];
            float am[8] = {ra0.x, ra0.y, ra0.z, ra0.w, ra1.x, ra1.y, ra1.z, ra1.w};
#pragma unroll
            for (int i = 0; i < 8; i++) {
                unsigned long long pa = pk2(am[i], am[i]);
                acc[i][0] = ffma2(pa, b01.x, acc[i][0]);
                acc[i][1] = ffma2(pa, b01.y, acc[i][1]);
                acc[i][2] = ffma2(pa, b23.x, acc[i][2]);
                acc[i][3] = ffma2(pa, b23.y, acc[i][3]);
            }
        }
        if (kt + 1 < NT) {
            store_s(buf ^ 1);
            __syncthreads();
            buf ^= 1;
        }
    }

    float bv[8];
#pragma unroll
    for (int j = 0; j < 4; j++) {
        float2 b2 = *(const float2*)(bias + n0 + tx * 8 + j * 2);
        bv[2 * j] = b2.x;
        bv[2 * j + 1] = b2.y;
    }
    float s = 0.f, q = 0.f;
#pragma unroll
    for (int i = 0; i < 8; i++) {
        int row = m0 + ty * 8 + i;
        if (row < M) {
            __half2* dst = (__half2*)(C + (size_t)row * HDIM + n0 + tx * 8);
#pragma unroll
            for (int j = 0; j < 4; j++) {
                float lo, hi;
                upk2(acc[i][j], lo, hi);
                lo += bv[2 * j];
                hi += bv[2 * j + 1];
                dst[j] = __floats2half2_rn(lo, hi);
                if (EPI1) {
                    s += lo + hi;
                    q += lo * lo + hi * hi;
                }
            }
        }
    }
    if (EPI1) {
        sds[tid] = (double)s;
        sds[256 + tid] = (double)q;
        __syncthreads();
        for (int o = 128; o > 0; o >>= 1) {
            if (tid < o) {
                sds[tid] += sds[tid + o];
                sds[256 + tid] += sds[256 + tid + o];
            }
            __syncthreads();
        }
        if (tid == 0) {
            atomicAdd(&g_scal[0], sds[0]);
            atomicAdd(&g_scal[1], sds[256]);
        }
    }
}

// Fold LN1 into W2: a_k = inv*ln1w_k; c_k = ln1b_k - mean*a_k; d = c @ W2.
__global__ __launch_bounds__(256) void k_prep(const float* __restrict__ lnw,
                                              const float* __restrict__ lnb,
                                              const float* __restrict__ W2, int M) {
    __shared__ float cs[HDIM];
    int t = threadIdx.x;
    double nn = (double)M * HDIM;
    double mm = g_scal[0] / nn;
    double var = g_scal[1] / nn - mm * mm;
    float mean = (float)mm;
    float inv = 1.f / ((float)sqrt(var) + EPS);
    float a = inv * lnw[t];
    float c = lnb[t] - mean * a;
    g_avec[t] = a;
    cs[t] = c;
    __syncthreads();
    float d = 0.f;
    for (int k = 0; k < HDIM; k++) d += cs[k] * W2[k * HDIM + t];
    g_dvec[t] = d;
}

// W2f[k][n] = a_k * W2[k][n]
__global__ __launch_bounds__(256) void k_scaleW(const float* __restrict__ W2,
                                                float* __restrict__ W2f) {
    int k = blockIdx.x, n = threadIdx.x;
    W2f[k * HDIM + n] = g_avec[k] * W2[k * HDIM + n];
}

// Final graph LayerNorm: read fp16 hout, write fp32 out (evict-first).
// One thread per 8 channels (uint4 of halfs).
__global__ __launch_bounds__(256) void k_ln2h(const __half* __restrict__ hout,
                                              const float* __restrict__ w,
                                              const float* __restrict__ b,
                                              float* __restrict__ out, int n8) {
    int i = blockIdx.x * blockDim.x + threadIdx.x;
    if (i >= n8) return;
    double n = (double)n8 * 8.0;
    double m = g_scal[2] / n;
    double var = g_scal[3] / n - m * m;
    float mean = (float)m;
    float inv = 1.f / ((float)sqrt(var) + EPS);
    uint4 u = __ldcs((const uint4*)hout + i);
    int c8 = (i & 31) * 8;     // channel base within row
    float4 w0 = *(const float4*)(w + c8);
    float4 w1 = *(const float4*)(w + c8 + 4);
    float4 b0 = *(const float4*)(b + c8);
    float4 b1 = *(const float4*)(b + c8 + 4);
    float2 f0 = __half22float2(*(__half2*)&u.x);
    float2 f1 = __half22float2(*(__half2*)&u.y);
    float2 f2 = __half22float2(*(__half2*)&u.z);
    float2 f3 = __half22float2(*(__half2*)&u.w);
    float4 o0, o1;
    o0.x = (f0.x - mean) * inv * w0.x + b0.x;
    o0.y = (f0.y - mean) * inv * w0.y + b0.y;
    o0.z = (f1.x - mean) * inv * w0.z + b0.z;
    o0.w = (f1.y - mean) * inv * w0.w + b0.w;
    o1.x = (f2.x - mean) * inv * w1.x + b1.x;
    o1.y = (f2.y - mean) * inv * w1.y + b1.y;
    o1.z = (f3.x - mean) * inv * w1.z + b1.z;
    o1.w = (f3.y - mean) * inv * w1.w + b1.w;
    __stcs((float4*)out + 2 * i, o0);
    __stcs((float4*)out + 2 * i + 1, o1);
}

extern "C" void kernel_launch(void* const* d_in, const int* in_sizes, int n_in,
                              void* d_out, int out_size) {
    const float* x = (const float*)d_in[0];
    const int* ei[4] = {(const int*)d_in[1], (const int*)d_in[3],
                        (const int*)d_in[5], (const int*)d_in[7]};
    const float* ew[4] = {(const float*)d_in[2], (const float*)d_in[4],
                          (const float*)d_in[6], (const float*)d_in[8]};
    const float* W1 = (const float*)d_in[9];
    const float* b1 = (const float*)d_in[10];
    const float* W2 = (const float*)d_in[11];
    const float* b2 = (const float*)d_in[12];
    const float* ln1w = (const float*)d_in[13];
    const float* ln1b = (const float*)d_in[14];
    const float* ln2w = (const float*)d_in[15];
    const float* ln2b = (const float*)d_in[16];

    int N = in_sizes[0] / F_IN;
    int E = in_sizes[1] / 2;
    int n2 = N * F_IN / 2;
    int n8 = N * HDIM / 8;

    __half *xh, *aggh, *h1h, *h2h, *hout;
    float *W2f, *dvec;
    int *rowptr, *pos, *deg;
    cudaGetSymbolAddress((void**)&xh, g_xh);
    cudaGetSymbolAddress((void**)&aggh, g_aggh);
    cudaGetSymbolAddress((void**)&h1h, g_h1h);
    cudaGetSymbolAddress((void**)&h2h, g_h2h);
    cudaGetSymbolAddress((void**)&hout, g_hout);
    cudaGetSymbolAddress((void**)&W2f, g_W2f);
    cudaGetSymbolAddress((void**)&dvec, g_dvec);
    cudaGetSymbolAddress((void**)&rowptr, g_rowptr);
    cudaGetSymbolAddress((void**)&pos, g_pos);
    cudaGetSymbolAddress((void**)&deg, g_deg);
    float* out = (float*)d_out;

    int e4Blocks = (4 * E + 255) / 256;
    int scanB = (N + 1023) / 1024;
    dim3 gbig(HDIM / 128, (N + 127) / 128);

    k_convert_zdeg<<<(n2 + 255) / 256, 256>>>(x, xh, n2, deg, N);
    k_hist_all<<<e4Blocks, 256>>>(ei[0], ei[1], ei[2], ei[3], deg, E);
    k_scan1z<<<scanB, 1024>>>(deg, rowptr, N);
    k_scan3b<<<scanB, 1024>>>(rowptr, pos, deg, N);
    k_fill_all<<<e4Blocks, 256>>>(ei[0], ew[0], ei[1], ew[1], ei[2], ew[2],
                                  ei[3], ew[3], pos, E);
    k_gather1<<<(N + 1) / 2, 64>>>((const uint2*)xh, rowptr, aggh, N);
    k_gemm_big<F_IN, F_IN, true><<<gbig, 256>>>(aggh, W1, b1, h1h, N);
    k_prep<<<1, 256>>>(ln1w, ln1b, W2, N);
    k_scaleW<<<HDIM, 256>>>(W2, W2f);
    k_gemm_big<HDIM, HDIM, false><<<gbig, 256>>>(h1h, W2f, dvec, h2h, N);
    k_gather2<<<(N + 1) / 2, 64>>>((const uint4*)h2h, rowptr, b2, hout, N);
    k_ln2h<<<(n8 + 255) / 256, 256>>>(hout, ln2w, ln2b, out, n8);
}